// round 14
// baseline (speedup 1.0000x reference)
#include <cuda_runtime.h>
#include <cuda_bf16.h>
#include <cstdint>
#include <cstddef>

#define BB 16
#define LL 32768
#define HH 64
#define NN 16
#define DMM 32

typedef unsigned long long u64;
typedef uint32_t u32;
typedef __nv_bfloat16 bf16;

// strides (elements)
#define USTR 72
#define MSTR 72
#define VSTR 72
#define ESTR 40
#define SSTR 40
#define YSTR 68
#define LSTR 521

// scan smem (total 227456 <= 232448)
#define SM_MH 0
#define SM_ML 9216
#define SM_VH 18432
#define SM_VL 23040
#define SM_EH 27648
#define SM_EL 32768
#define SM_UB0 37888
#define SM_SLOC 74752
#define SM_UB1 141440
#define SM_UB2 178304
#define SM_SINH 141440
#define SM_SINL 182400
#define SM_GBUF 223360
#define SM_TOT 227456
#define UBUF_HALF 18432

// linear-mma v2 smem (128-l tile): W 18KB | bias | XH/XL 36.9KB ; Ys overlays X
#define LM_WTH 0
#define LM_WTL 9216
#define LM_BS 18432
#define LM_XH 18688
#define LM_XL 37120
#define LM_YS 18688
#define LM_TOT 55552
#define XSTR 72
#define WSTR 72
#define YL 136

// ---------------- scratch ----------------
__device__ bf16 g_uh[(size_t)BB * HH * LL];
__device__ bf16 g_ul[(size_t)BB * HH * LL];
__device__ float g_z[(size_t)BB * HH * LL];
__device__ bf16 g_Mh[HH * 4096], g_Ml[HH * 4096];
__device__ bf16 g_Vh[HH * 2048], g_Vl[HH * 2048];
__device__ bf16 g_Eh[HH * 2048], g_El[HH * 2048];
__device__ bf16 g_WH[4096], g_WL[4096];
__device__ float2 g_w64c[HH * 16], g_wGc[HH * 16];
__device__ float g_gamma[BB * HH], g_beta[BB * HH];

// ---------------- helpers ----------------
__device__ __forceinline__ float gelu_f(float x) {
    float x3 = x * x * x;
    float z = 0.7978845608028654f * fmaf(0.044715f, x3, x);
    float az = fabsf(z);
    float e = __expf(2.0f * az);
    float t = 1.0f - __fdividef(2.0f, e + 1.0f);
    t = copysignf(t, z);
    return 0.5f * x * (1.0f + t);
}
__device__ __forceinline__ void bsplit(float v, bf16* ph, bf16* pl) {
    bf16 hi = __float2bfloat16(v);
    *ph = hi; *pl = __float2bfloat16(v - __bfloat162float(hi));
}
__device__ __forceinline__ u32 pk2bf(bf16 a, bf16 b) {
    __nv_bfloat162 v; v.x = a; v.y = b; return *reinterpret_cast<u32*>(&v);
}
__device__ __forceinline__ float2 cmulf(float2 a, float2 b) {
    return make_float2(a.x * b.x - a.y * b.y, a.x * b.y + a.y * b.x);
}
__device__ __forceinline__ float2 cpowf(float2 w, int e) {
    float2 r = make_float2(1.0f, 0.0f);
    while (e) {
        if (e & 1) r = cmulf(r, w);
        w = cmulf(w, w);
        e >>= 1;
    }
    return r;
}
__device__ __forceinline__ void mma16816(float* c, const u32* a, const u32* b) {
    asm volatile(
        "mma.sync.aligned.m16n8k16.row.col.f32.bf16.bf16.f32 "
        "{%0,%1,%2,%3}, {%4,%5,%6,%7}, {%8,%9}, {%0,%1,%2,%3};"
        : "+f"(c[0]), "+f"(c[1]), "+f"(c[2]), "+f"(c[3])
        : "r"(a[0]), "r"(a[1]), "r"(a[2]), "r"(a[3]), "r"(b[0]), "r"(b[1]));
}
__device__ __forceinline__ void ldsm_x4(u32* r, const bf16* base, int stride,
                                        int r0, int k0, int lane) {
    const bf16* p = base + (r0 + (lane & 15)) * stride + k0 + (lane >> 4) * 8;
    u32 addr = (u32)__cvta_generic_to_shared(p);
    asm volatile("ldmatrix.sync.aligned.m8n8.x4.shared.b16 {%0,%1,%2,%3}, [%4];"
        : "=r"(r[0]), "=r"(r[1]), "=r"(r[2]), "=r"(r[3]) : "r"(addr));
}
__device__ __forceinline__ void ldsm_x2(u32* r, const bf16* base, int stride,
                                        int n0, int k0, int lane) {
    const bf16* p = base + (n0 + (lane & 7)) * stride + k0 + ((lane >> 3) & 1) * 8;
    u32 addr = (u32)__cvta_generic_to_shared(p);
    asm volatile("ldmatrix.sync.aligned.m8n8.x2.shared.b16 {%0,%1}, [%2];"
        : "=r"(r[0]), "=r"(r[1]) : "r"(addr));
}
__device__ __forceinline__ void cpasync16(void* sdst, const void* gsrc) {
    u32 s = (u32)__cvta_generic_to_shared(sdst);
    asm volatile("cp.async.cg.shared.global [%0], [%1], 16;" :: "r"(s), "l"(gsrc) : "memory");
}
#define CP_COMMIT() asm volatile("cp.async.commit_group;" ::: "memory")
#define CP_WAIT(n) asm volatile("cp.async.wait_group %0;" :: "n"(n) : "memory")

__device__ __forceinline__ void stage_async(const bf16* guh, const bf16* gul,
                                            int q, int t, bf16* UH, bf16* UL) {
    #pragma unroll
    for (int k = 0; k < 2; k++) {
        int f = t + k * 512;
        int c = f >> 3, i0 = (f & 7) * 8;
        cpasync16(&UH[c * USTR + i0], guh + q * 8192 + c * 64 + i0);
        cpasync16(&UL[c * USTR + i0], gul + q * 8192 + c * 64 + i0);
    }
}

// ---------------- K0: per-h tables ----------------
__global__ void k_setup_tab(const float* __restrict__ log_dt,
                            const float* __restrict__ A_re, const float* __restrict__ A_im,
                            const float* __restrict__ C_re, const float* __restrict__ C_im,
                            const float* __restrict__ Dv)
{
    int h = blockIdx.x;
    int j = threadIdx.x;
    __shared__ float2 wf[NN];
    __shared__ float2 c2f[NN];
    __shared__ float Ks[64];

    double dt = exp((double)log_dt[h]);
    if (j < NN) {
        int i = h * NN + j;
        float ar = A_re[i], ai = A_im[i];
        double mre = dt * (double)ar, mim = dt * (double)ai;
        double e1 = exp(mre);
        float wr = (float)(e1 * cos(mim)), wi = (float)(e1 * sin(mim));
        wf[j] = make_float2(wr, wi);
        float den = ar * ar + ai * ai;
        float nr = wr - 1.0f, ni = wi;
        float qr = (nr * ar + ni * ai) / den, qi = (ni * ar - nr * ai) / den;
        float cr = C_re[i], ci = C_im[i];
        c2f[j] = make_float2(2.0f * (cr * qr - ci * qi), 2.0f * (cr * qi + ci * qr));
        float2 w64 = cpowf(make_float2(wr, wi), 64);
        g_w64c[h * 16 + j] = w64;
        g_wGc[h * 16 + j] = cpowf(w64, 16);
    }
    __syncthreads();

    float kacc = 0.0f;
    for (int n = 0; n < NN; n++) {
        float2 w = wf[n];
        float2 c2 = c2f[n];
        float2 wj = cpowf(w, j);
        kacc += c2.x * wj.x - c2.y * wj.y;
        float2 wj1 = cmulf(wj, w);
        bsplit(c2.x * wj1.x - c2.y * wj1.y,
               &g_Eh[h * 2048 + j * 32 + n], &g_El[h * 2048 + j * 32 + n]);
        bsplit(-(c2.x * wj1.y + c2.y * wj1.x),
               &g_Eh[h * 2048 + j * 32 + 16 + n], &g_El[h * 2048 + j * 32 + 16 + n]);
        float2 wv = cpowf(w, 63 - j);
        bsplit(wv.x, &g_Vh[h * 2048 + n * 64 + j], &g_Vl[h * 2048 + n * 64 + j]);
        bsplit(wv.y, &g_Vh[h * 2048 + (16 + n) * 64 + j], &g_Vl[h * 2048 + (16 + n) * 64 + j]);
    }
    Ks[j] = kacc;
    __syncthreads();

    float dD = Dv[h];
    for (int i2 = 0; i2 < 64; i2++) {
        float m = (i2 < j) ? Ks[j - i2] : (i2 == j ? Ks[0] + dD : 0.0f);
        bsplit(m, &g_Mh[h * 4096 + j * 64 + i2], &g_Ml[h * 4096 + j * 64 + i2]);
    }
}

// ---------------- K1: conditioning MLP + FiLM + W pre-split ----------------
__global__ void k_setup_mlp(const float* __restrict__ cp,
                            const float* __restrict__ W0, const float* __restrict__ b0,
                            const float* __restrict__ W1, const float* __restrict__ b1,
                            const float* __restrict__ W2, const float* __restrict__ b2,
                            const float* __restrict__ W_film, const float* __restrict__ b_film,
                            const float* __restrict__ W_lin)
{
    __shared__ float c0[BB * DMM];
    __shared__ float c1[BB * DMM];
    int t = threadIdx.x;
    for (int i = t; i < 4096; i += 256) {
        int k = i >> 6, h = i & 63;
        bsplit(W_lin[i], &g_WH[h * 64 + k], &g_WL[h * 64 + k]);
    }
    for (int i = t; i < BB * DMM; i += blockDim.x) {
        int b = i / DMM, d = i % DMM;
        float v = fmaf(cp[b * 2 + 0], W0[d], fmaf(cp[b * 2 + 1], W0[DMM + d], b0[d]));
        c0[i] = gelu_f(v);
    }
    __syncthreads();
    for (int i = t; i < BB * DMM; i += blockDim.x) {
        int b = i / DMM, d = i % DMM;
        float v = b1[d];
        for (int k = 0; k < DMM; k++) v = fmaf(c0[b * DMM + k], W1[k * DMM + d], v);
        c1[i] = gelu_f(v);
    }
    __syncthreads();
    for (int i = t; i < BB * DMM; i += blockDim.x) {
        int b = i / DMM, d = i % DMM;
        float v = b2[d];
        for (int k = 0; k < DMM; k++) v = fmaf(c1[b * DMM + k], W2[k * DMM + d], v);
        c0[i] = gelu_f(v);
    }
    __syncthreads();
    for (int i = t; i < BB * 2 * HH; i += blockDim.x) {
        int b = i / (2 * HH), j = i % (2 * HH);
        float v = b_film[j];
        for (int k = 0; k < DMM; k++) v = fmaf(c0[b * DMM + k], W_film[k * 2 * HH + j], v);
        if (j < HH) g_gamma[b * HH + j] = v;
        else        g_beta[b * HH + j - HH] = v;
    }
}

// ---------------- K2 v2: 128-l tile, 3 blocks/SM, cp.async W staging ----------------
__global__ __launch_bounds__(256, 3) void k_linear_mma(const float* __restrict__ x,
                                                       const float* __restrict__ bias)
{
    extern __shared__ char sm[];
    bf16* WtH = (bf16*)(sm + LM_WTH);
    bf16* WtL = (bf16*)(sm + LM_WTL);
    float* bs = (float*)(sm + LM_BS);
    bf16* XH = (bf16*)(sm + LM_XH);
    bf16* XL = (bf16*)(sm + LM_XL);
    bf16* YsH = (bf16*)(sm + LM_YS);       // overlays XH/XL after MMA
    bf16* YsL = YsH + 64 * YL;

    int t = threadIdx.x, wid = t >> 5, lane = t & 31;
    int b = blockIdx.x >> 8, tile = blockIdx.x & 255;
    int l0 = tile * 128;

    // W staging via cp.async (pre-split bf16, pure copies with pad)
    #pragma unroll
    for (int k = 0; k < 2; k++) {
        int f = t + k * 256;               // 0..511 : 64 rows x 8 chunks
        int r = f >> 3, c8 = (f & 7) * 8;
        cpasync16(&WtH[r * WSTR + c8], g_WH + r * 64 + c8);
        cpasync16(&WtL[r * WSTR + c8], g_WL + r * 64 + c8);
    }
    CP_COMMIT();
    if (t < 64) bs[t] = bias[t];

    // x staging (fp32 -> split bf16)
    const float4* xg4 = (const float4*)(x + ((size_t)b * LL + l0) * HH);
    #pragma unroll
    for (int kk = 0; kk < 8; kk++) {
        int f = t + kk * 256;              // 0..2047
        float4 v = xg4[f];
        int l = f >> 4, i0 = (f & 15) * 4;
        bf16 h0, l0b, h1, l1b, h2, l2b, h3, l3b;
        bsplit(v.x, &h0, &l0b); bsplit(v.y, &h1, &l1b);
        bsplit(v.z, &h2, &l2b); bsplit(v.w, &h3, &l3b);
        *(u32*)&XH[l * XSTR + i0] = pk2bf(h0, h1);
        *(u32*)&XH[l * XSTR + i0 + 2] = pk2bf(h2, h3);
        *(u32*)&XL[l * XSTR + i0] = pk2bf(l0b, l1b);
        *(u32*)&XL[l * XSTR + i0 + 2] = pk2bf(l2b, l3b);
    }
    CP_WAIT(0);
    __syncthreads();

    // warp tile: 16 l x 64 h
    float C[8][4];
    #pragma unroll
    for (int nt = 0; nt < 8; nt++) {
        int c0 = nt * 8 + (lane & 3) * 2;
        C[nt][0] = bs[c0]; C[nt][1] = bs[c0 + 1];
        C[nt][2] = bs[c0]; C[nt][3] = bs[c0 + 1];
    }
    #pragma unroll
    for (int kt = 0; kt < 4; kt++) {
        int k0 = kt * 16;
        u32 ah[4], al[4];
        ldsm_x4(ah, XH, XSTR, wid * 16, k0, lane);
        ldsm_x4(al, XL, XSTR, wid * 16, k0, lane);
        #pragma unroll
        for (int nt = 0; nt < 8; nt++) {
            u32 bh[2], bl[2];
            ldsm_x2(bh, WtH, WSTR, nt * 8, k0, lane);
            ldsm_x2(bl, WtL, WSTR, nt * 8, k0, lane);
            mma16816(C[nt], ah, bh);
            mma16816(C[nt], ah, bl);
            mma16816(C[nt], al, bh);
        }
    }
    __syncthreads();   // all X reads done before Ys overlay writes
    #pragma unroll
    for (int nt = 0; nt < 8; nt++) {
        int l = wid * 16 + (lane >> 2);
        int h0 = nt * 8 + (lane & 3) * 2;
        #pragma unroll
        for (int e = 0; e < 4; e++) {
            int hh = h0 + (e & 1);
            int ll = l + (e >> 1) * 8;
            bf16 hi, lo;
            bsplit(gelu_f(C[nt][e]), &hi, &lo);
            YsH[hh * YL + ll] = hi;
            YsL[hh * YL + ll] = lo;
        }
    }
    __syncthreads();
    // coalesced plane writes: 64 h x 128 l bf16 = 1024 uint4 per plane
    #pragma unroll
    for (int i = t; i < 1024; i += 256) {
        int h = i >> 4, q = i & 15;
        size_t base = ((size_t)b * HH + h) * LL + l0 + q * 8;
        *(uint4*)(g_uh + base) = *(const uint4*)&YsH[h * YL + q * 8];
        *(uint4*)(g_ul + base) = *(const uint4*)&YsL[h * YL + q * 8];
    }
}

// ---------------- K3: fused scan; pair-processed quarters, cp.async staging ----------------
__global__ __launch_bounds__(512) void k_scan_mma()
{
    extern __shared__ char smem[];
    bf16* MHs = (bf16*)(smem + SM_MH);
    bf16* MLs = (bf16*)(smem + SM_ML);
    bf16* VHs = (bf16*)(smem + SM_VH);
    bf16* VLs = (bf16*)(smem + SM_VL);
    bf16* EHs = (bf16*)(smem + SM_EH);
    bf16* ELs = (bf16*)(smem + SM_EL);
    float* SLOC = (float*)(smem + SM_SLOC);
    bf16* SINH = (bf16*)(smem + SM_SINH);
    bf16* SINL = (bf16*)(smem + SM_SINL);
    float2* GBUF = (float2*)(smem + SM_GBUF);
    bf16* B0H = (bf16*)(smem + SM_UB0);
    bf16* B0L = (bf16*)(smem + SM_UB0 + UBUF_HALF);
    bf16* B1H = (bf16*)(smem + SM_UB1);
    bf16* B1L = (bf16*)(smem + SM_UB1 + UBUF_HALF);
    bf16* B2H = (bf16*)(smem + SM_UB2);
    bf16* B2L = (bf16*)(smem + SM_UB2 + UBUF_HALF);

    int t = threadIdx.x;
    int bh = blockIdx.x;
    int h = bh & 63;
    int wid = t >> 5, lane = t & 31;
    int cloc = wid * 8;

    const bf16* guh = g_uh + (size_t)bh * LL;
    const bf16* gul = g_ul + (size_t)bh * LL;

    stage_async(guh, gul, 0, t, B0H, B0L); CP_COMMIT();
    stage_async(guh, gul, 1, t, B1H, B1L); CP_COMMIT();
    stage_async(guh, gul, 2, t, B2H, B2L); CP_COMMIT();

    {
        const u32* gmh = (const u32*)(g_Mh + (size_t)h * 4096);
        const u32* gml = (const u32*)(g_Ml + (size_t)h * 4096);
        u32* smh = (u32*)MHs; u32* sml = (u32*)MLs;
        for (int i = t; i < 2048; i += 512) {
            int r = i >> 5, c = i & 31;
            smh[r * 36 + c] = gmh[i]; sml[r * 36 + c] = gml[i];
        }
        const u32* gvh = (const u32*)(g_Vh + (size_t)h * 2048);
        const u32* gvl = (const u32*)(g_Vl + (size_t)h * 2048);
        u32* svh = (u32*)VHs; u32* svl = (u32*)VLs;
        for (int i = t; i < 1024; i += 512) {
            int r = i >> 5, c = i & 31;
            svh[r * 36 + c] = gvh[i]; svl[r * 36 + c] = gvl[i];
        }
        const u32* geh = (const u32*)(g_Eh + (size_t)h * 2048);
        const u32* gel = (const u32*)(g_El + (size_t)h * 2048);
        u32* seh = (u32*)EHs; u32* sel = (u32*)ELs;
        for (int i = t; i < 1024; i += 512) {
            int r = i >> 4, c = i & 15;
            seh[r * 20 + c] = geh[i]; sel[r * 20 + c] = gel[i];
        }
    }

    float Yreg[64];
    #pragma unroll
    for (int i = 0; i < 64; i++) Yreg[i] = 0.0f;

#define PAIR(P, UHA, ULA, UHB, ULB)                                            \
    {                                                                          \
        float C1a[2][4] = {}, C1b[2][4] = {};                                  \
        _Pragma("unroll")                                                      \
        for (int kt = 0; kt < 4; kt++) {                                       \
            int k0 = kt * 16;                                                  \
            u32 bah[2], bal[2], bbh[2], bbl[2];                                \
            ldsm_x2(bah, UHA, USTR, cloc, k0, lane);                           \
            ldsm_x2(bal, ULA, USTR, cloc, k0, lane);                           \
            ldsm_x2(bbh, UHB, USTR, cloc, k0, lane);                           \
            ldsm_x2(bbl, ULB, USTR, cloc, k0, lane);                           \
            _Pragma("unroll")                                                  \
            for (int mt = 0; mt < 2; mt++) {                                   \
                u32 ah[4], al[4];                                              \
                ldsm_x4(ah, VHs, VSTR, mt * 16, k0, lane);                     \
                ldsm_x4(al, VLs, VSTR, mt * 16, k0, lane);                     \
                mma16816(C1a[mt], ah, bah); mma16816(C1a[mt], ah, bal);        \
                mma16816(C1a[mt], al, bah);                                    \
                mma16816(C1b[mt], ah, bbh); mma16816(C1b[mt], ah, bbl);        \
                mma16816(C1b[mt], al, bbh);                                    \
            }                                                                  \
            _Pragma("unroll")                                                  \
            for (int mt = 0; mt < 4; mt++) {                                   \
                if (kt > mt) continue;                                         \
                u32 ah[4], al[4];                                              \
                ldsm_x4(ah, MHs, MSTR, mt * 16, k0, lane);                     \
                ldsm_x4(al, MLs, MSTR, mt * 16, k0, lane);                     \
                float* Ca = &Yreg[(2 * (P)) * 16 + mt * 4];                    \
                float* Cb = &Yreg[(2 * (P) + 1) * 16 + mt * 4];                \
                mma16816(Ca, ah, bah); mma16816(Ca, ah, bal);                  \
                mma16816(Ca, al, bah);                                         \
                mma16816(Cb, ah, bbh); mma16816(Cb, ah, bbl);                  \
                mma16816(Cb, al, bbh);                                         \
            }                                                                  \
        }                                                                      \
        _Pragma("unroll")                                                      \
        for (int mt = 0; mt < 2; mt++) {                                       \
            int r = mt * 16 + (lane >> 2);                                     \
            int ca = (2 * (P)) * 128 + cloc + (lane & 3) * 2;                  \
            int cb = (2 * (P) + 1) * 128 + cloc + (lane & 3) * 2;              \
            SLOC[r * LSTR + ca] = C1a[mt][0];                                  \
            SLOC[r * LSTR + ca + 1] = C1a[mt][1];                              \
            SLOC[(r + 8) * LSTR + ca] = C1a[mt][2];                            \
            SLOC[(r + 8) * LSTR + ca + 1] = C1a[mt][3];                        \
            SLOC[r * LSTR + cb] = C1b[mt][0];                                  \
            SLOC[r * LSTR + cb + 1] = C1b[mt][1];                              \
            SLOC[(r + 8) * LSTR + cb] = C1b[mt][2];                            \
            SLOC[(r + 8) * LSTR + cb + 1] = C1b[mt][3];                        \
        }                                                                      \
    }

    CP_WAIT(1);
    __syncthreads();
    PAIR(0, B0H, B0L, B1H, B1L)
    __syncthreads();
    stage_async(guh, gul, 3, t, B0H, B0L); CP_COMMIT();
    CP_WAIT(0);
    __syncthreads();
    PAIR(1, B2H, B2L, B0H, B0L)
    __syncthreads();
#undef PAIR

    {
        int n = t & 15, g = t >> 4;
        float2 w64 = g_w64c[h * 16 + n];
        float sr = 0.f, si = 0.f;
        for (int m = 0; m < 16; m++) {
            int c = g * 16 + m;
            float xr = SLOC[n * LSTR + c], xi = SLOC[(16 + n) * LSTR + c];
            float nr = fmaf(w64.x, sr, fmaf(-w64.y, si, xr));
            si = fmaf(w64.x, si, fmaf(w64.y, sr, xi));
            sr = nr;
        }
        GBUF[g * 16 + n] = make_float2(sr, si);
        __syncthreads();
        if (t < 16) {
            float2 wG = g_wGc[h * 16 + t];
            float pr = 0.f, pi = 0.f;
            for (int gg = 0; gg < 32; gg++) {
                float2 tm = GBUF[gg * 16 + t];
                GBUF[gg * 16 + t] = make_float2(pr, pi);
                float nr = fmaf(wG.x, pr, fmaf(-wG.y, pi, tm.x));
                pi = fmaf(wG.x, pi, fmaf(wG.y, pr, tm.y));
                pr = nr;
            }
        }
        __syncthreads();
        float2 I = GBUF[g * 16 + n];
        sr = I.x; si = I.y;
        for (int m = 0; m < 16; m++) {
            int c = g * 16 + m;
            bsplit(sr, &SINH[c * SSTR + n], &SINL[c * SSTR + n]);
            bsplit(si, &SINH[c * SSTR + 16 + n], &SINL[c * SSTR + 16 + n]);
            float xr = SLOC[n * LSTR + c], xi = SLOC[(16 + n) * LSTR + c];
            float nr = fmaf(w64.x, sr, fmaf(-w64.y, si, xr));
            si = fmaf(w64.x, si, fmaf(w64.y, sr, xi));
            sr = nr;
        }
    }
    __syncthreads();

    float gam = g_gamma[bh];
    float bet = g_beta[bh];
    float* Ys = SLOC;
    float4* gz4 = (float4*)(g_z + (size_t)bh * LL);

    #pragma unroll
    for (int q = 0; q < 4; q++) {
        int cglob = q * 128 + cloc;
        #pragma unroll
        for (int kt = 0; kt < 2; kt++) {
            int k0 = kt * 16;
            u32 bh_[2], bl_[2];
            ldsm_x2(bh_, SINH, SSTR, cglob, k0, lane);
            ldsm_x2(bl_, SINL, SSTR, cglob, k0, lane);
            #pragma unroll
            for (int mt = 0; mt < 4; mt++) {
                u32 ah[4], al[4];
                ldsm_x4(ah, EHs, ESTR, mt * 16, k0, lane);
                ldsm_x4(al, ELs, ESTR, mt * 16, k0, lane);
                float* Cm = &Yreg[q * 16 + mt * 4];
                mma16816(Cm, ah, bh_);
                mma16816(Cm, ah, bl_);
                mma16816(Cm, al, bh_);
            }
        }
        #pragma unroll
        for (int mt = 0; mt < 4; mt++) {
            int j = mt * 16 + (lane >> 2);
            int cc = cloc + (lane & 3) * 2;
            const float* Cm = &Yreg[q * 16 + mt * 4];
            Ys[cc * YSTR + j] = fmaf(Cm[0], gam, bet);
            Ys[(cc + 1) * YSTR + j] = fmaf(Cm[1], gam, bet);
            Ys[cc * YSTR + j + 8] = fmaf(Cm[2], gam, bet);
            Ys[(cc + 1) * YSTR + j + 8] = fmaf(Cm[3], gam, bet);
        }
        __syncthreads();
        #pragma unroll
        for (int k = 0; k < 4; k++) {
            int f = t + k * 512;
            int c = f >> 4, qq = f & 15;
            float4 o = *(const float4*)&Ys[c * YSTR + qq * 4];
            gz4[q * 2048 + f] = o;
        }
        __syncthreads();
    }
}

// ---------------- K4: out = x * gelu(z) ----------------
__global__ __launch_bounds__(256) void k_epilogue(const float* __restrict__ x,
                                                  float* __restrict__ out)
{
    __shared__ float zt[64 * 65];
    int t = threadIdx.x;
    int b = blockIdx.x >> 9;
    int tile = blockIdx.x & 511;
    int l0 = tile * 64;
    #pragma unroll
    for (int i = t; i < 1024; i += 256) {
        int hh = i >> 4, q = i & 15;
        float4 v = *reinterpret_cast<const float4*>(
            g_z + ((size_t)b * HH + hh) * LL + l0 + 4 * q);
        float* d = zt + hh * 65 + 4 * q;
        d[0] = v.x; d[1] = v.y; d[2] = v.z; d[3] = v.w;
    }
    __syncthreads();
    #pragma unroll
    for (int i = t; i < 1024; i += 256) {
        int l = i >> 4, hq = i & 15;
        float z0 = zt[(4 * hq + 0) * 65 + l];
        float z1 = zt[(4 * hq + 1) * 65 + l];
        float z2 = zt[(4 * hq + 2) * 65 + l];
        float z3 = zt[(4 * hq + 3) * 65 + l];
        size_t base = ((size_t)b * LL + l0 + l) * HH + 4 * hq;
        float4 xv = *reinterpret_cast<const float4*>(x + base);
        float4 o;
        o.x = xv.x * gelu_f(z0);
        o.y = xv.y * gelu_f(z1);
        o.z = xv.z * gelu_f(z2);
        o.w = xv.w * gelu_f(z3);
        *reinterpret_cast<float4*>(out + base) = o;
    }
}

// ---------------- launch ----------------
extern "C" void kernel_launch(void* const* d_in, const int* in_sizes, int n_in,
                              void* d_out, int out_size)
{
    const float* x      = (const float*)d_in[0];
    const float* cp     = (const float*)d_in[1];
    const float* W0     = (const float*)d_in[2];
    const float* b0     = (const float*)d_in[3];
    const float* W1     = (const float*)d_in[4];
    const float* b1     = (const float*)d_in[5];
    const float* W2     = (const float*)d_in[6];
    const float* b2     = (const float*)d_in[7];
    const float* W_lin  = (const float*)d_in[8];
    const float* b_lin  = (const float*)d_in[9];
    const float* log_dt = (const float*)d_in[10];
    const float* A_re   = (const float*)d_in[11];
    const float* A_im   = (const float*)d_in[12];
    const float* C_re   = (const float*)d_in[13];
    const float* C_im   = (const float*)d_in[14];
    const float* Dv     = (const float*)d_in[15];
    const float* W_film = (const float*)d_in[16];
    const float* b_film = (const float*)d_in[17];
    float* out = (float*)d_out;

    cudaFuncSetAttribute(k_linear_mma, cudaFuncAttributeMaxDynamicSharedMemorySize, LM_TOT);
    cudaFuncSetAttribute(k_scan_mma, cudaFuncAttributeMaxDynamicSharedMemorySize, SM_TOT);

    k_setup_tab<<<HH, 64>>>(log_dt, A_re, A_im, C_re, C_im, Dv);
    k_setup_mlp<<<1, 256>>>(cp, W0, b0, W1, b1, W2, b2, W_film, b_film, W_lin);
    k_linear_mma<<<BB * (LL / 128), 256, LM_TOT>>>(x, b_lin);
    k_scan_mma<<<BB * HH, 512, SM_TOT>>>();
    k_epilogue<<<BB * (LL / 64), 256>>>(x, out);
}

// round 15
// speedup vs baseline: 1.3060x; 1.3060x over previous
#include <cuda_runtime.h>
#include <cuda_bf16.h>
#include <cstdint>
#include <cstddef>

#define BB 16
#define LL 32768
#define HH 64
#define NN 16
#define DMM 32

typedef unsigned long long u64;
typedef uint32_t u32;
typedef __nv_bfloat16 bf16;

// strides (elements)
#define USTR 72
#define MSTR 72
#define VSTR 72
#define ESTR 40
#define SSTR 40
#define YSTR 68
#define LSTR 521

// scan smem (total 227456 <= 232448)
#define SM_MH 0
#define SM_ML 9216
#define SM_VH 18432
#define SM_VL 23040
#define SM_EH 27648
#define SM_EL 32768
#define SM_UB0 37888
#define SM_SLOC 74752
#define SM_UB1 141440
#define SM_UB2 178304
#define SM_SINH 141440
#define SM_SINL 182400
#define SM_GBUF 223360
#define SM_TOT 227456
#define UBUF_HALF 18432

// linear-mma smem (256-l tile, 512 threads)
#define LM_WTH 0
#define LM_WTL 9216
#define LM_BS 18432
#define LM_XH 18688
#define LM_XL 55552
#define LM_YS 18688
#define LM_TOT 92416
#define XSTR 72
#define WSTR 72
#define YL 264

// ---------------- scratch ----------------
__device__ bf16 g_uh[(size_t)BB * HH * LL];
__device__ bf16 g_ul[(size_t)BB * HH * LL];
__device__ float g_z[(size_t)BB * HH * LL];
__device__ bf16 g_Mh[HH * 4096], g_Ml[HH * 4096];
__device__ bf16 g_Vh[HH * 2048], g_Vl[HH * 2048];
__device__ bf16 g_Eh[HH * 2048], g_El[HH * 2048];
__device__ bf16 g_WH[4096], g_WL[4096];
__device__ float2 g_w64c[HH * 16], g_wGc[HH * 16];
__device__ float g_gamma[BB * HH], g_beta[BB * HH];

// ---------------- helpers ----------------
__device__ __forceinline__ float gelu_f(float x) {
    float x3 = x * x * x;
    float z = 0.7978845608028654f * fmaf(0.044715f, x3, x);
    float az = fabsf(z);
    float e = __expf(2.0f * az);
    float t = 1.0f - __fdividef(2.0f, e + 1.0f);
    t = copysignf(t, z);
    return 0.5f * x * (1.0f + t);
}
__device__ __forceinline__ void bsplit(float v, bf16* ph, bf16* pl) {
    bf16 hi = __float2bfloat16(v);
    *ph = hi; *pl = __float2bfloat16(v - __bfloat162float(hi));
}
__device__ __forceinline__ u32 pk2bf(bf16 a, bf16 b) {
    __nv_bfloat162 v; v.x = a; v.y = b; return *reinterpret_cast<u32*>(&v);
}
__device__ __forceinline__ float2 cmulf(float2 a, float2 b) {
    return make_float2(a.x * b.x - a.y * b.y, a.x * b.y + a.y * b.x);
}
__device__ __forceinline__ float2 cpowf(float2 w, int e) {
    float2 r = make_float2(1.0f, 0.0f);
    while (e) {
        if (e & 1) r = cmulf(r, w);
        w = cmulf(w, w);
        e >>= 1;
    }
    return r;
}
__device__ __forceinline__ void mma16816(float* c, const u32* a, const u32* b) {
    asm volatile(
        "mma.sync.aligned.m16n8k16.row.col.f32.bf16.bf16.f32 "
        "{%0,%1,%2,%3}, {%4,%5,%6,%7}, {%8,%9}, {%0,%1,%2,%3};"
        : "+f"(c[0]), "+f"(c[1]), "+f"(c[2]), "+f"(c[3])
        : "r"(a[0]), "r"(a[1]), "r"(a[2]), "r"(a[3]), "r"(b[0]), "r"(b[1]));
}
__device__ __forceinline__ void ldsm_x4(u32* r, const bf16* base, int stride,
                                        int r0, int k0, int lane) {
    const bf16* p = base + (r0 + (lane & 15)) * stride + k0 + (lane >> 4) * 8;
    u32 addr = (u32)__cvta_generic_to_shared(p);
    asm volatile("ldmatrix.sync.aligned.m8n8.x4.shared.b16 {%0,%1,%2,%3}, [%4];"
        : "=r"(r[0]), "=r"(r[1]), "=r"(r[2]), "=r"(r[3]) : "r"(addr));
}
__device__ __forceinline__ void ldsm_x2(u32* r, const bf16* base, int stride,
                                        int n0, int k0, int lane) {
    const bf16* p = base + (n0 + (lane & 7)) * stride + k0 + ((lane >> 3) & 1) * 8;
    u32 addr = (u32)__cvta_generic_to_shared(p);
    asm volatile("ldmatrix.sync.aligned.m8n8.x2.shared.b16 {%0,%1}, [%2];"
        : "=r"(r[0]), "=r"(r[1]) : "r"(addr));
}
__device__ __forceinline__ void cpasync16(void* sdst, const void* gsrc) {
    u32 s = (u32)__cvta_generic_to_shared(sdst);
    asm volatile("cp.async.cg.shared.global [%0], [%1], 16;" :: "r"(s), "l"(gsrc) : "memory");
}
#define CP_COMMIT() asm volatile("cp.async.commit_group;" ::: "memory")
#define CP_WAIT(n) asm volatile("cp.async.wait_group %0;" :: "n"(n) : "memory")

__device__ __forceinline__ void stage_async(const bf16* guh, const bf16* gul,
                                            int q, int t, bf16* UH, bf16* UL) {
    #pragma unroll
    for (int k = 0; k < 2; k++) {
        int f = t + k * 512;
        int c = f >> 3, i0 = (f & 7) * 8;
        cpasync16(&UH[c * USTR + i0], guh + q * 8192 + c * 64 + i0);
        cpasync16(&UL[c * USTR + i0], gul + q * 8192 + c * 64 + i0);
    }
}

// ---------------- K0: per-h tables ----------------
__global__ void k_setup_tab(const float* __restrict__ log_dt,
                            const float* __restrict__ A_re, const float* __restrict__ A_im,
                            const float* __restrict__ C_re, const float* __restrict__ C_im,
                            const float* __restrict__ Dv)
{
    int h = blockIdx.x;
    int j = threadIdx.x;
    __shared__ float2 wf[NN];
    __shared__ float2 c2f[NN];
    __shared__ float Ks[64];

    double dt = exp((double)log_dt[h]);
    if (j < NN) {
        int i = h * NN + j;
        float ar = A_re[i], ai = A_im[i];
        double mre = dt * (double)ar, mim = dt * (double)ai;
        double e1 = exp(mre);
        float wr = (float)(e1 * cos(mim)), wi = (float)(e1 * sin(mim));
        wf[j] = make_float2(wr, wi);
        float den = ar * ar + ai * ai;
        float nr = wr - 1.0f, ni = wi;
        float qr = (nr * ar + ni * ai) / den, qi = (ni * ar - nr * ai) / den;
        float cr = C_re[i], ci = C_im[i];
        c2f[j] = make_float2(2.0f * (cr * qr - ci * qi), 2.0f * (cr * qi + ci * qr));
        float2 w64 = cpowf(make_float2(wr, wi), 64);
        g_w64c[h * 16 + j] = w64;
        g_wGc[h * 16 + j] = cpowf(w64, 16);
    }
    __syncthreads();

    float kacc = 0.0f;
    for (int n = 0; n < NN; n++) {
        float2 w = wf[n];
        float2 c2 = c2f[n];
        float2 wj = cpowf(w, j);
        kacc += c2.x * wj.x - c2.y * wj.y;
        float2 wj1 = cmulf(wj, w);
        bsplit(c2.x * wj1.x - c2.y * wj1.y,
               &g_Eh[h * 2048 + j * 32 + n], &g_El[h * 2048 + j * 32 + n]);
        bsplit(-(c2.x * wj1.y + c2.y * wj1.x),
               &g_Eh[h * 2048 + j * 32 + 16 + n], &g_El[h * 2048 + j * 32 + 16 + n]);
        float2 wv = cpowf(w, 63 - j);
        bsplit(wv.x, &g_Vh[h * 2048 + n * 64 + j], &g_Vl[h * 2048 + n * 64 + j]);
        bsplit(wv.y, &g_Vh[h * 2048 + (16 + n) * 64 + j], &g_Vl[h * 2048 + (16 + n) * 64 + j]);
    }
    Ks[j] = kacc;
    __syncthreads();

    float dD = Dv[h];
    for (int i2 = 0; i2 < 64; i2++) {
        float m = (i2 < j) ? Ks[j - i2] : (i2 == j ? Ks[0] + dD : 0.0f);
        bsplit(m, &g_Mh[h * 4096 + j * 64 + i2], &g_Ml[h * 4096 + j * 64 + i2]);
    }
}

// ---------------- K1: conditioning MLP + FiLM + W pre-split ----------------
__global__ void k_setup_mlp(const float* __restrict__ cp,
                            const float* __restrict__ W0, const float* __restrict__ b0,
                            const float* __restrict__ W1, const float* __restrict__ b1,
                            const float* __restrict__ W2, const float* __restrict__ b2,
                            const float* __restrict__ W_film, const float* __restrict__ b_film,
                            const float* __restrict__ W_lin)
{
    __shared__ float c0[BB * DMM];
    __shared__ float c1[BB * DMM];
    int t = threadIdx.x;
    for (int i = t; i < 4096; i += 256) {
        int k = i >> 6, h = i & 63;
        bsplit(W_lin[i], &g_WH[h * 64 + k], &g_WL[h * 64 + k]);
    }
    for (int i = t; i < BB * DMM; i += blockDim.x) {
        int b = i / DMM, d = i % DMM;
        float v = fmaf(cp[b * 2 + 0], W0[d], fmaf(cp[b * 2 + 1], W0[DMM + d], b0[d]));
        c0[i] = gelu_f(v);
    }
    __syncthreads();
    for (int i = t; i < BB * DMM; i += blockDim.x) {
        int b = i / DMM, d = i % DMM;
        float v = b1[d];
        for (int k = 0; k < DMM; k++) v = fmaf(c0[b * DMM + k], W1[k * DMM + d], v);
        c1[i] = gelu_f(v);
    }
    __syncthreads();
    for (int i = t; i < BB * DMM; i += blockDim.x) {
        int b = i / DMM, d = i % DMM;
        float v = b2[d];
        for (int k = 0; k < DMM; k++) v = fmaf(c1[b * DMM + k], W2[k * DMM + d], v);
        c0[i] = gelu_f(v);
    }
    __syncthreads();
    for (int i = t; i < BB * 2 * HH; i += blockDim.x) {
        int b = i / (2 * HH), j = i % (2 * HH);
        float v = b_film[j];
        for (int k = 0; k < DMM; k++) v = fmaf(c0[b * DMM + k], W_film[k * 2 * HH + j], v);
        if (j < HH) g_gamma[b * HH + j] = v;
        else        g_beta[b * HH + j - HH] = v;
    }
}

// ---------------- K2: 256-l tile, 512 threads, 2 blocks/SM ----------------
__global__ __launch_bounds__(512, 2) void k_linear_mma(const float* __restrict__ x,
                                                       const float* __restrict__ bias)
{
    extern __shared__ char sm[];
    bf16* WtH = (bf16*)(sm + LM_WTH);
    bf16* WtL = (bf16*)(sm + LM_WTL);
    float* bs = (float*)(sm + LM_BS);
    bf16* XH = (bf16*)(sm + LM_XH);
    bf16* XL = (bf16*)(sm + LM_XL);
    bf16* YsH = (bf16*)(sm + LM_YS);   // overlays XH/XL after MMA
    bf16* YsL = YsH + 64 * YL;

    int t = threadIdx.x, wid = t >> 5, lane = t & 31;
    int b = blockIdx.x >> 7, tile = blockIdx.x & 127;
    int l0 = tile * 256;

    // stage pre-split W (u32 copies with pad)
    {
        const u32* gwh = (const u32*)g_WH;
        const u32* gwl = (const u32*)g_WL;
        u32* swh = (u32*)WtH; u32* swl = (u32*)WtL;
        for (int i = t; i < 2048; i += 512) {
            int r = i >> 5, c = i & 31;
            swh[r * 36 + c] = gwh[i];
            swl[r * 36 + c] = gwl[i];
        }
    }
    if (t < 64) bs[t] = bias[t];
    // stage x split: 4096 float4s
    const float4* xg4 = (const float4*)(x + ((size_t)b * LL + l0) * HH);
    #pragma unroll
    for (int kk = 0; kk < 8; kk++) {
        int f = t + kk * 512;
        float4 v = xg4[f];
        int l = f >> 4, i0 = (f & 15) * 4;
        bf16 h0, l0b, h1, l1b, h2, l2b, h3, l3b;
        bsplit(v.x, &h0, &l0b); bsplit(v.y, &h1, &l1b);
        bsplit(v.z, &h2, &l2b); bsplit(v.w, &h3, &l3b);
        *(u32*)&XH[l * XSTR + i0] = pk2bf(h0, h1);
        *(u32*)&XH[l * XSTR + i0 + 2] = pk2bf(h2, h3);
        *(u32*)&XL[l * XSTR + i0] = pk2bf(l0b, l1b);
        *(u32*)&XL[l * XSTR + i0 + 2] = pk2bf(l2b, l3b);
    }
    __syncthreads();

    // warp tile: 16 l x 64 h (16 warps cover 256 l)
    float C[8][4];
    #pragma unroll
    for (int nt = 0; nt < 8; nt++) {
        int c0 = nt * 8 + (lane & 3) * 2;
        C[nt][0] = bs[c0]; C[nt][1] = bs[c0 + 1];
        C[nt][2] = bs[c0]; C[nt][3] = bs[c0 + 1];
    }
    #pragma unroll
    for (int kt = 0; kt < 4; kt++) {
        int k0 = kt * 16;
        u32 ah[4], al[4];
        ldsm_x4(ah, XH, XSTR, wid * 16, k0, lane);
        ldsm_x4(al, XL, XSTR, wid * 16, k0, lane);
        #pragma unroll
        for (int nt = 0; nt < 8; nt++) {
            u32 bh[2], bl[2];
            ldsm_x2(bh, WtH, WSTR, nt * 8, k0, lane);
            ldsm_x2(bl, WtL, WSTR, nt * 8, k0, lane);
            mma16816(C[nt], ah, bh);
            mma16816(C[nt], ah, bl);
            mma16816(C[nt], al, bh);
        }
    }
    __syncthreads();   // all X reads done before Ys overlay writes
    #pragma unroll
    for (int nt = 0; nt < 8; nt++) {
        int l = wid * 16 + (lane >> 2);
        int h0 = nt * 8 + (lane & 3) * 2;
        #pragma unroll
        for (int e = 0; e < 4; e++) {
            int hh = h0 + (e & 1);
            int ll = l + (e >> 1) * 8;
            bf16 hi, lo;
            bsplit(gelu_f(C[nt][e]), &hi, &lo);
            YsH[hh * YL + ll] = hi;
            YsL[hh * YL + ll] = lo;
        }
    }
    __syncthreads();
    // coalesced plane writes: 64 h x 256 l = 2048 uint4 per plane
    #pragma unroll
    for (int i = t; i < 2048; i += 512) {
        int h = i >> 5, q = i & 31;
        size_t base = ((size_t)b * HH + h) * LL + l0 + q * 8;
        *(uint4*)(g_uh + base) = *(const uint4*)&YsH[h * YL + q * 8];
        *(uint4*)(g_ul + base) = *(const uint4*)&YsL[h * YL + q * 8];
    }
}

// ---------------- K3: fused scan; pair-processed quarters, cp.async staging ----------------
__global__ __launch_bounds__(512) void k_scan_mma()
{
    extern __shared__ char smem[];
    bf16* MHs = (bf16*)(smem + SM_MH);
    bf16* MLs = (bf16*)(smem + SM_ML);
    bf16* VHs = (bf16*)(smem + SM_VH);
    bf16* VLs = (bf16*)(smem + SM_VL);
    bf16* EHs = (bf16*)(smem + SM_EH);
    bf16* ELs = (bf16*)(smem + SM_EL);
    float* SLOC = (float*)(smem + SM_SLOC);
    bf16* SINH = (bf16*)(smem + SM_SINH);
    bf16* SINL = (bf16*)(smem + SM_SINL);
    float2* GBUF = (float2*)(smem + SM_GBUF);
    bf16* B0H = (bf16*)(smem + SM_UB0);
    bf16* B0L = (bf16*)(smem + SM_UB0 + UBUF_HALF);
    bf16* B1H = (bf16*)(smem + SM_UB1);
    bf16* B1L = (bf16*)(smem + SM_UB1 + UBUF_HALF);
    bf16* B2H = (bf16*)(smem + SM_UB2);
    bf16* B2L = (bf16*)(smem + SM_UB2 + UBUF_HALF);

    int t = threadIdx.x;
    int bh = blockIdx.x;
    int h = bh & 63;
    int wid = t >> 5, lane = t & 31;
    int cloc = wid * 8;

    const bf16* guh = g_uh + (size_t)bh * LL;
    const bf16* gul = g_ul + (size_t)bh * LL;

    stage_async(guh, gul, 0, t, B0H, B0L); CP_COMMIT();
    stage_async(guh, gul, 1, t, B1H, B1L); CP_COMMIT();
    stage_async(guh, gul, 2, t, B2H, B2L); CP_COMMIT();

    {
        const u32* gmh = (const u32*)(g_Mh + (size_t)h * 4096);
        const u32* gml = (const u32*)(g_Ml + (size_t)h * 4096);
        u32* smh = (u32*)MHs; u32* sml = (u32*)MLs;
        for (int i = t; i < 2048; i += 512) {
            int r = i >> 5, c = i & 31;
            smh[r * 36 + c] = gmh[i]; sml[r * 36 + c] = gml[i];
        }
        const u32* gvh = (const u32*)(g_Vh + (size_t)h * 2048);
        const u32* gvl = (const u32*)(g_Vl + (size_t)h * 2048);
        u32* svh = (u32*)VHs; u32* svl = (u32*)VLs;
        for (int i = t; i < 1024; i += 512) {
            int r = i >> 5, c = i & 31;
            svh[r * 36 + c] = gvh[i]; svl[r * 36 + c] = gvl[i];
        }
        const u32* geh = (const u32*)(g_Eh + (size_t)h * 2048);
        const u32* gel = (const u32*)(g_El + (size_t)h * 2048);
        u32* seh = (u32*)EHs; u32* sel = (u32*)ELs;
        for (int i = t; i < 1024; i += 512) {
            int r = i >> 4, c = i & 15;
            seh[r * 20 + c] = geh[i]; sel[r * 20 + c] = gel[i];
        }
    }

    float Yreg[64];
    #pragma unroll
    for (int i = 0; i < 64; i++) Yreg[i] = 0.0f;

#define PAIR(P, UHA, ULA, UHB, ULB)                                            \
    {                                                                          \
        float C1a[2][4] = {}, C1b[2][4] = {};                                  \
        _Pragma("unroll")                                                      \
        for (int kt = 0; kt < 4; kt++) {                                       \
            int k0 = kt * 16;                                                  \
            u32 bah[2], bal[2], bbh[2], bbl[2];                                \
            ldsm_x2(bah, UHA, USTR, cloc, k0, lane);                           \
            ldsm_x2(bal, ULA, USTR, cloc, k0, lane);                           \
            ldsm_x2(bbh, UHB, USTR, cloc, k0, lane);                           \
            ldsm_x2(bbl, ULB, USTR, cloc, k0, lane);                           \
            _Pragma("unroll")                                                  \
            for (int mt = 0; mt < 2; mt++) {                                   \
                u32 ah[4], al[4];                                              \
                ldsm_x4(ah, VHs, VSTR, mt * 16, k0, lane);                     \
                ldsm_x4(al, VLs, VSTR, mt * 16, k0, lane);                     \
                mma16816(C1a[mt], ah, bah); mma16816(C1a[mt], ah, bal);        \
                mma16816(C1a[mt], al, bah);                                    \
                mma16816(C1b[mt], ah, bbh); mma16816(C1b[mt], ah, bbl);        \
                mma16816(C1b[mt], al, bbh);                                    \
            }                                                                  \
            _Pragma("unroll")                                                  \
            for (int mt = 0; mt < 4; mt++) {                                   \
                if (kt > mt) continue;                                         \
                u32 ah[4], al[4];                                              \
                ldsm_x4(ah, MHs, MSTR, mt * 16, k0, lane);                     \
                ldsm_x4(al, MLs, MSTR, mt * 16, k0, lane);                     \
                float* Ca = &Yreg[(2 * (P)) * 16 + mt * 4];                    \
                float* Cb = &Yreg[(2 * (P) + 1) * 16 + mt * 4];                \
                mma16816(Ca, ah, bah); mma16816(Ca, ah, bal);                  \
                mma16816(Ca, al, bah);                                         \
                mma16816(Cb, ah, bbh); mma16816(Cb, ah, bbl);                  \
                mma16816(Cb, al, bbh);                                         \
            }                                                                  \
        }                                                                      \
        _Pragma("unroll")                                                      \
        for (int mt = 0; mt < 2; mt++) {                                       \
            int r = mt * 16 + (lane >> 2);                                     \
            int ca = (2 * (P)) * 128 + cloc + (lane & 3) * 2;                  \
            int cb = (2 * (P) + 1) * 128 + cloc + (lane & 3) * 2;              \
            SLOC[r * LSTR + ca] = C1a[mt][0];                                  \
            SLOC[r * LSTR + ca + 1] = C1a[mt][1];                              \
            SLOC[(r + 8) * LSTR + ca] = C1a[mt][2];                            \
            SLOC[(r + 8) * LSTR + ca + 1] = C1a[mt][3];                        \
            SLOC[r * LSTR + cb] = C1b[mt][0];                                  \
            SLOC[r * LSTR + cb + 1] = C1b[mt][1];                              \
            SLOC[(r + 8) * LSTR + cb] = C1b[mt][2];                            \
            SLOC[(r + 8) * LSTR + cb + 1] = C1b[mt][3];                        \
        }                                                                      \
    }

    CP_WAIT(1);
    __syncthreads();
    PAIR(0, B0H, B0L, B1H, B1L)
    __syncthreads();
    stage_async(guh, gul, 3, t, B0H, B0L); CP_COMMIT();
    CP_WAIT(0);
    __syncthreads();
    PAIR(1, B2H, B2L, B0H, B0L)
    __syncthreads();
#undef PAIR

    {
        int n = t & 15, g = t >> 4;
        float2 w64 = g_w64c[h * 16 + n];
        float sr = 0.f, si = 0.f;
        for (int m = 0; m < 16; m++) {
            int c = g * 16 + m;
            float xr = SLOC[n * LSTR + c], xi = SLOC[(16 + n) * LSTR + c];
            float nr = fmaf(w64.x, sr, fmaf(-w64.y, si, xr));
            si = fmaf(w64.x, si, fmaf(w64.y, sr, xi));
            sr = nr;
        }
        GBUF[g * 16 + n] = make_float2(sr, si);
        __syncthreads();
        if (t < 16) {
            float2 wG = g_wGc[h * 16 + t];
            float pr = 0.f, pi = 0.f;
            for (int gg = 0; gg < 32; gg++) {
                float2 tm = GBUF[gg * 16 + t];
                GBUF[gg * 16 + t] = make_float2(pr, pi);
                float nr = fmaf(wG.x, pr, fmaf(-wG.y, pi, tm.x));
                pi = fmaf(wG.x, pi, fmaf(wG.y, pr, tm.y));
                pr = nr;
            }
        }
        __syncthreads();
        float2 I = GBUF[g * 16 + n];
        sr = I.x; si = I.y;
        for (int m = 0; m < 16; m++) {
            int c = g * 16 + m;
            bsplit(sr, &SINH[c * SSTR + n], &SINL[c * SSTR + n]);
            bsplit(si, &SINH[c * SSTR + 16 + n], &SINL[c * SSTR + 16 + n]);
            float xr = SLOC[n * LSTR + c], xi = SLOC[(16 + n) * LSTR + c];
            float nr = fmaf(w64.x, sr, fmaf(-w64.y, si, xr));
            si = fmaf(w64.x, si, fmaf(w64.y, sr, xi));
            sr = nr;
        }
    }
    __syncthreads();

    float gam = g_gamma[bh];
    float bet = g_beta[bh];
    float* Ys = SLOC;
    float4* gz4 = (float4*)(g_z + (size_t)bh * LL);

    #pragma unroll
    for (int q = 0; q < 4; q++) {
        int cglob = q * 128 + cloc;
        #pragma unroll
        for (int kt = 0; kt < 2; kt++) {
            int k0 = kt * 16;
            u32 bh_[2], bl_[2];
            ldsm_x2(bh_, SINH, SSTR, cglob, k0, lane);
            ldsm_x2(bl_, SINL, SSTR, cglob, k0, lane);
            #pragma unroll
            for (int mt = 0; mt < 4; mt++) {
                u32 ah[4], al[4];
                ldsm_x4(ah, EHs, ESTR, mt * 16, k0, lane);
                ldsm_x4(al, ELs, ESTR, mt * 16, k0, lane);
                float* Cm = &Yreg[q * 16 + mt * 4];
                mma16816(Cm, ah, bh_);
                mma16816(Cm, ah, bl_);
                mma16816(Cm, al, bh_);
            }
        }
        #pragma unroll
        for (int mt = 0; mt < 4; mt++) {
            int j = mt * 16 + (lane >> 2);
            int cc = cloc + (lane & 3) * 2;
            const float* Cm = &Yreg[q * 16 + mt * 4];
            Ys[cc * YSTR + j] = fmaf(Cm[0], gam, bet);
            Ys[(cc + 1) * YSTR + j] = fmaf(Cm[1], gam, bet);
            Ys[cc * YSTR + j + 8] = fmaf(Cm[2], gam, bet);
            Ys[(cc + 1) * YSTR + j + 8] = fmaf(Cm[3], gam, bet);
        }
        __syncthreads();
        #pragma unroll
        for (int k = 0; k < 4; k++) {
            int f = t + k * 512;
            int c = f >> 4, qq = f & 15;
            float4 o = *(const float4*)&Ys[c * YSTR + qq * 4];
            gz4[q * 2048 + f] = o;
        }
        __syncthreads();
    }
}

// ---------------- K4: out = x * gelu(z) ----------------
__global__ __launch_bounds__(256) void k_epilogue(const float* __restrict__ x,
                                                  float* __restrict__ out)
{
    __shared__ float zt[64 * 65];
    int t = threadIdx.x;
    int b = blockIdx.x >> 9;
    int tile = blockIdx.x & 511;
    int l0 = tile * 64;
    #pragma unroll
    for (int i = t; i < 1024; i += 256) {
        int hh = i >> 4, q = i & 15;
        float4 v = *reinterpret_cast<const float4*>(
            g_z + ((size_t)b * HH + hh) * LL + l0 + 4 * q);
        float* d = zt + hh * 65 + 4 * q;
        d[0] = v.x; d[1] = v.y; d[2] = v.z; d[3] = v.w;
    }
    __syncthreads();
    #pragma unroll
    for (int i = t; i < 1024; i += 256) {
        int l = i >> 4, hq = i & 15;
        float z0 = zt[(4 * hq + 0) * 65 + l];
        float z1 = zt[(4 * hq + 1) * 65 + l];
        float z2 = zt[(4 * hq + 2) * 65 + l];
        float z3 = zt[(4 * hq + 3) * 65 + l];
        size_t base = ((size_t)b * LL + l0 + l) * HH + 4 * hq;
        float4 xv = *reinterpret_cast<const float4*>(x + base);
        float4 o;
        o.x = xv.x * gelu_f(z0);
        o.y = xv.y * gelu_f(z1);
        o.z = xv.z * gelu_f(z2);
        o.w = xv.w * gelu_f(z3);
        *reinterpret_cast<float4*>(out + base) = o;
    }
}

// ---------------- launch ----------------
extern "C" void kernel_launch(void* const* d_in, const int* in_sizes, int n_in,
                              void* d_out, int out_size)
{
    const float* x      = (const float*)d_in[0];
    const float* cp     = (const float*)d_in[1];
    const float* W0     = (const float*)d_in[2];
    const float* b0     = (const float*)d_in[3];
    const float* W1     = (const float*)d_in[4];
    const float* b1     = (const float*)d_in[5];
    const float* W2     = (const float*)d_in[6];
    const float* b2     = (const float*)d_in[7];
    const float* W_lin  = (const float*)d_in[8];
    const float* b_lin  = (const float*)d_in[9];
    const float* log_dt = (const float*)d_in[10];
    const float* A_re   = (const float*)d_in[11];
    const float* A_im   = (const float*)d_in[12];
    const float* C_re   = (const float*)d_in[13];
    const float* C_im   = (const float*)d_in[14];
    const float* Dv     = (const float*)d_in[15];
    const float* W_film = (const float*)d_in[16];
    const float* b_film = (const float*)d_in[17];
    float* out = (float*)d_out;

    cudaFuncSetAttribute(k_linear_mma, cudaFuncAttributeMaxDynamicSharedMemorySize, LM_TOT);
    cudaFuncSetAttribute(k_scan_mma, cudaFuncAttributeMaxDynamicSharedMemorySize, SM_TOT);

    k_setup_tab<<<HH, 64>>>(log_dt, A_re, A_im, C_re, C_im, Dv);
    k_setup_mlp<<<1, 256>>>(cp, W0, b0, W1, b1, W2, b2, W_film, b_film, W_lin);
    k_linear_mma<<<BB * (LL / 256), 512, LM_TOT>>>(x, b_lin);
    k_scan_mma<<<BB * HH, 512, SM_TOT>>>();
    k_epilogue<<<BB * (LL / 64), 256>>>(x, out);
}

// round 16
// speedup vs baseline: 1.3949x; 1.0681x over previous
#include <cuda_runtime.h>
#include <cuda_bf16.h>
#include <cstdint>
#include <cstddef>

#define BB 16
#define LL 32768
#define HH 64
#define NN 16
#define DMM 32

typedef unsigned long long u64;
typedef uint32_t u32;
typedef __nv_bfloat16 bf16;

// strides (elements)
#define USTR 72
#define MSTR 72
#define VSTR 72
#define ESTR 40
#define SSTR 40
#define LSTR 521

// scan smem (total 227456 <= 232448)
#define SM_MH 0
#define SM_ML 9216
#define SM_VH 18432
#define SM_VL 23040
#define SM_EH 27648
#define SM_EL 32768
#define SM_UB0 37888
#define SM_SLOC 74752
#define SM_UB1 141440
#define SM_UB2 178304
#define SM_SINH 141440
#define SM_SINL 182400
#define SM_GBUF 223360
#define SM_TOT 227456
#define UBUF_HALF 18432

// linear-mma smem (256-l tile, 256 threads)
#define LM_WTH 0
#define LM_WTL 9216
#define LM_BS 18432
#define LM_XH 18688
#define LM_XL 55552
#define LM_YS 18688
#define LM_TOT 92416
#define XSTR 72
#define WSTR 72
#define YL 264

// ---------------- scratch ----------------
__device__ bf16 g_uh[(size_t)BB * HH * LL];
__device__ bf16 g_ul[(size_t)BB * HH * LL];
__device__ float g_z[(size_t)BB * HH * LL];
__device__ bf16 g_Mh[HH * 4096], g_Ml[HH * 4096];
__device__ bf16 g_Vh[HH * 2048], g_Vl[HH * 2048];
__device__ bf16 g_Eh[HH * 2048], g_El[HH * 2048];
__device__ bf16 g_WH[4096], g_WL[4096];
__device__ float2 g_w64c[HH * 16], g_wGc[HH * 16];
__device__ float g_gamma[BB * HH], g_beta[BB * HH];

// ---------------- helpers ----------------
__device__ __forceinline__ float gelu_f(float x) {
    float x3 = x * x * x;
    float z = 0.7978845608028654f * fmaf(0.044715f, x3, x);
    float az = fabsf(z);
    float e = __expf(2.0f * az);
    float t = 1.0f - __fdividef(2.0f, e + 1.0f);
    t = copysignf(t, z);
    return 0.5f * x * (1.0f + t);
}
__device__ __forceinline__ void bsplit(float v, bf16* ph, bf16* pl) {
    bf16 hi = __float2bfloat16(v);
    *ph = hi; *pl = __float2bfloat16(v - __bfloat162float(hi));
}
__device__ __forceinline__ u32 pk2bf(bf16 a, bf16 b) {
    __nv_bfloat162 v; v.x = a; v.y = b; return *reinterpret_cast<u32*>(&v);
}
__device__ __forceinline__ float2 cmulf(float2 a, float2 b) {
    return make_float2(a.x * b.x - a.y * b.y, a.x * b.y + a.y * b.x);
}
__device__ __forceinline__ float2 cpowf(float2 w, int e) {
    float2 r = make_float2(1.0f, 0.0f);
    while (e) {
        if (e & 1) r = cmulf(r, w);
        w = cmulf(w, w);
        e >>= 1;
    }
    return r;
}
__device__ __forceinline__ void mma16816(float* c, const u32* a, const u32* b) {
    asm volatile(
        "mma.sync.aligned.m16n8k16.row.col.f32.bf16.bf16.f32 "
        "{%0,%1,%2,%3}, {%4,%5,%6,%7}, {%8,%9}, {%0,%1,%2,%3};"
        : "+f"(c[0]), "+f"(c[1]), "+f"(c[2]), "+f"(c[3])
        : "r"(a[0]), "r"(a[1]), "r"(a[2]), "r"(a[3]), "r"(b[0]), "r"(b[1]));
}
__device__ __forceinline__ void ldsm_x4(u32* r, const bf16* base, int stride,
                                        int r0, int k0, int lane) {
    const bf16* p = base + (r0 + (lane & 15)) * stride + k0 + (lane >> 4) * 8;
    u32 addr = (u32)__cvta_generic_to_shared(p);
    asm volatile("ldmatrix.sync.aligned.m8n8.x4.shared.b16 {%0,%1,%2,%3}, [%4];"
        : "=r"(r[0]), "=r"(r[1]), "=r"(r[2]), "=r"(r[3]) : "r"(addr));
}
__device__ __forceinline__ void ldsm_x2(u32* r, const bf16* base, int stride,
                                        int n0, int k0, int lane) {
    const bf16* p = base + (n0 + (lane & 7)) * stride + k0 + ((lane >> 3) & 1) * 8;
    u32 addr = (u32)__cvta_generic_to_shared(p);
    asm volatile("ldmatrix.sync.aligned.m8n8.x2.shared.b16 {%0,%1}, [%2];"
        : "=r"(r[0]), "=r"(r[1]) : "r"(addr));
}
__device__ __forceinline__ void cpasync16(void* sdst, const void* gsrc) {
    u32 s = (u32)__cvta_generic_to_shared(sdst);
    asm volatile("cp.async.cg.shared.global [%0], [%1], 16;" :: "r"(s), "l"(gsrc) : "memory");
}
#define CP_COMMIT() asm volatile("cp.async.commit_group;" ::: "memory")
#define CP_WAIT(n) asm volatile("cp.async.wait_group %0;" :: "n"(n) : "memory")

__device__ __forceinline__ void stage_async(const bf16* guh, const bf16* gul,
                                            int q, int t, bf16* UH, bf16* UL) {
    #pragma unroll
    for (int k = 0; k < 2; k++) {
        int f = t + k * 512;
        int c = f >> 3, i0 = (f & 7) * 8;
        cpasync16(&UH[c * USTR + i0], guh + q * 8192 + c * 64 + i0);
        cpasync16(&UL[c * USTR + i0], gul + q * 8192 + c * 64 + i0);
    }
}

// ---------------- K0: per-h tables ----------------
__global__ void k_setup_tab(const float* __restrict__ log_dt,
                            const float* __restrict__ A_re, const float* __restrict__ A_im,
                            const float* __restrict__ C_re, const float* __restrict__ C_im,
                            const float* __restrict__ Dv)
{
    int h = blockIdx.x;
    int j = threadIdx.x;
    __shared__ float2 wf[NN];
    __shared__ float2 c2f[NN];
    __shared__ float Ks[64];

    double dt = exp((double)log_dt[h]);
    if (j < NN) {
        int i = h * NN + j;
        float ar = A_re[i], ai = A_im[i];
        double mre = dt * (double)ar, mim = dt * (double)ai;
        double e1 = exp(mre);
        float wr = (float)(e1 * cos(mim)), wi = (float)(e1 * sin(mim));
        wf[j] = make_float2(wr, wi);
        float den = ar * ar + ai * ai;
        float nr = wr - 1.0f, ni = wi;
        float qr = (nr * ar + ni * ai) / den, qi = (ni * ar - nr * ai) / den;
        float cr = C_re[i], ci = C_im[i];
        c2f[j] = make_float2(2.0f * (cr * qr - ci * qi), 2.0f * (cr * qi + ci * qr));
        float2 w64 = cpowf(make_float2(wr, wi), 64);
        g_w64c[h * 16 + j] = w64;
        g_wGc[h * 16 + j] = cpowf(w64, 16);
    }
    __syncthreads();

    float kacc = 0.0f;
    for (int n = 0; n < NN; n++) {
        float2 w = wf[n];
        float2 c2 = c2f[n];
        float2 wj = cpowf(w, j);
        kacc += c2.x * wj.x - c2.y * wj.y;
        float2 wj1 = cmulf(wj, w);
        bsplit(c2.x * wj1.x - c2.y * wj1.y,
               &g_Eh[h * 2048 + j * 32 + n], &g_El[h * 2048 + j * 32 + n]);
        bsplit(-(c2.x * wj1.y + c2.y * wj1.x),
               &g_Eh[h * 2048 + j * 32 + 16 + n], &g_El[h * 2048 + j * 32 + 16 + n]);
        float2 wv = cpowf(w, 63 - j);
        bsplit(wv.x, &g_Vh[h * 2048 + n * 64 + j], &g_Vl[h * 2048 + n * 64 + j]);
        bsplit(wv.y, &g_Vh[h * 2048 + (16 + n) * 64 + j], &g_Vl[h * 2048 + (16 + n) * 64 + j]);
    }
    Ks[j] = kacc;
    __syncthreads();

    float dD = Dv[h];
    for (int i2 = 0; i2 < 64; i2++) {
        float m = (i2 < j) ? Ks[j - i2] : (i2 == j ? Ks[0] + dD : 0.0f);
        bsplit(m, &g_Mh[h * 4096 + j * 64 + i2], &g_Ml[h * 4096 + j * 64 + i2]);
    }
}

// ---------------- K1: conditioning MLP + FiLM + W pre-split ----------------
__global__ void k_setup_mlp(const float* __restrict__ cp,
                            const float* __restrict__ W0, const float* __restrict__ b0,
                            const float* __restrict__ W1, const float* __restrict__ b1,
                            const float* __restrict__ W2, const float* __restrict__ b2,
                            const float* __restrict__ W_film, const float* __restrict__ b_film,
                            const float* __restrict__ W_lin)
{
    __shared__ float c0[BB * DMM];
    __shared__ float c1[BB * DMM];
    int t = threadIdx.x;
    for (int i = t; i < 4096; i += 256) {
        int k = i >> 6, h = i & 63;
        bsplit(W_lin[i], &g_WH[h * 64 + k], &g_WL[h * 64 + k]);
    }
    for (int i = t; i < BB * DMM; i += blockDim.x) {
        int b = i / DMM, d = i % DMM;
        float v = fmaf(cp[b * 2 + 0], W0[d], fmaf(cp[b * 2 + 1], W0[DMM + d], b0[d]));
        c0[i] = gelu_f(v);
    }
    __syncthreads();
    for (int i = t; i < BB * DMM; i += blockDim.x) {
        int b = i / DMM, d = i % DMM;
        float v = b1[d];
        for (int k = 0; k < DMM; k++) v = fmaf(c0[b * DMM + k], W1[k * DMM + d], v);
        c1[i] = gelu_f(v);
    }
    __syncthreads();
    for (int i = t; i < BB * DMM; i += blockDim.x) {
        int b = i / DMM, d = i % DMM;
        float v = b2[d];
        for (int k = 0; k < DMM; k++) v = fmaf(c1[b * DMM + k], W2[k * DMM + d], v);
        c0[i] = gelu_f(v);
    }
    __syncthreads();
    for (int i = t; i < BB * 2 * HH; i += blockDim.x) {
        int b = i / (2 * HH), j = i % (2 * HH);
        float v = b_film[j];
        for (int k = 0; k < DMM; k++) v = fmaf(c0[b * DMM + k], W_film[k * 2 * HH + j], v);
        if (j < HH) g_gamma[b * HH + j] = v;
        else        g_beta[b * HH + j - HH] = v;
    }
}

// ---------------- K2: 256-l tile, 256 threads, cp.async W + batched x prefetch ----------------
__global__ __launch_bounds__(256, 2) void k_linear_mma(const float* __restrict__ x,
                                                       const float* __restrict__ bias)
{
    extern __shared__ char sm[];
    bf16* WtH = (bf16*)(sm + LM_WTH);
    bf16* WtL = (bf16*)(sm + LM_WTL);
    float* bs = (float*)(sm + LM_BS);
    bf16* XH = (bf16*)(sm + LM_XH);
    bf16* XL = (bf16*)(sm + LM_XL);
    bf16* YsH = (bf16*)(sm + LM_YS);   // overlays XH/XL after MMA
    bf16* YsL = YsH + 64 * YL;

    int t = threadIdx.x, wid = t >> 5, lane = t & 31;
    int b = blockIdx.x >> 7, tile = blockIdx.x & 127;
    int l0 = tile * 256;

    // W staging via cp.async (pre-split bf16, pure 16B copies with pad)
    #pragma unroll
    for (int k = 0; k < 2; k++) {
        int f = t + k * 256;               // 0..511 : 64 rows x 8 chunks
        int r = f >> 3, c8 = (f & 7) * 8;
        cpasync16(&WtH[r * WSTR + c8], g_WH + r * 64 + c8);
        cpasync16(&WtL[r * WSTR + c8], g_WL + r * 64 + c8);
    }
    CP_COMMIT();
    if (t < 64) bs[t] = bias[t];

    // batch x prefetch: 16 independent LDG.128 (MLP=16)
    const float4* xg4 = (const float4*)(x + ((size_t)b * LL + l0) * HH);
    float4 v[16];
    #pragma unroll
    for (int kk = 0; kk < 16; kk++) v[kk] = xg4[t + kk * 256];
    // convert + STS
    #pragma unroll
    for (int kk = 0; kk < 16; kk++) {
        int f = t + kk * 256;
        int l = f >> 4, i0 = (f & 15) * 4;
        bf16 h0, l0b, h1, l1b, h2, l2b, h3, l3b;
        bsplit(v[kk].x, &h0, &l0b); bsplit(v[kk].y, &h1, &l1b);
        bsplit(v[kk].z, &h2, &l2b); bsplit(v[kk].w, &h3, &l3b);
        *(u32*)&XH[l * XSTR + i0] = pk2bf(h0, h1);
        *(u32*)&XH[l * XSTR + i0 + 2] = pk2bf(h2, h3);
        *(u32*)&XL[l * XSTR + i0] = pk2bf(l0b, l1b);
        *(u32*)&XL[l * XSTR + i0 + 2] = pk2bf(l2b, l3b);
    }
    CP_WAIT(0);
    __syncthreads();

    // warp tile: 32 l x 64 h (8 warps cover 256 l)
    float C[2][8][4];
    #pragma unroll
    for (int mt = 0; mt < 2; mt++)
        #pragma unroll
        for (int nt = 0; nt < 8; nt++) {
            int c0 = nt * 8 + (lane & 3) * 2;
            C[mt][nt][0] = bs[c0]; C[mt][nt][1] = bs[c0 + 1];
            C[mt][nt][2] = bs[c0]; C[mt][nt][3] = bs[c0 + 1];
        }
    #pragma unroll
    for (int kt = 0; kt < 4; kt++) {
        int k0 = kt * 16;
        u32 ah[2][4], al[2][4];
        #pragma unroll
        for (int mt = 0; mt < 2; mt++) {
            ldsm_x4(ah[mt], XH, XSTR, wid * 32 + mt * 16, k0, lane);
            ldsm_x4(al[mt], XL, XSTR, wid * 32 + mt * 16, k0, lane);
        }
        #pragma unroll
        for (int nt = 0; nt < 8; nt++) {
            u32 bh[2], bl[2];
            ldsm_x2(bh, WtH, WSTR, nt * 8, k0, lane);
            ldsm_x2(bl, WtL, WSTR, nt * 8, k0, lane);
            #pragma unroll
            for (int mt = 0; mt < 2; mt++) {
                mma16816(C[mt][nt], ah[mt], bh);
                mma16816(C[mt][nt], ah[mt], bl);
                mma16816(C[mt][nt], al[mt], bh);
            }
        }
    }
    __syncthreads();   // all X reads done before Ys overlay writes
    #pragma unroll
    for (int mt = 0; mt < 2; mt++)
        #pragma unroll
        for (int nt = 0; nt < 8; nt++) {
            int l = wid * 32 + mt * 16 + (lane >> 2);
            int h0 = nt * 8 + (lane & 3) * 2;
            #pragma unroll
            for (int e = 0; e < 4; e++) {
                int hh = h0 + (e & 1);
                int ll = l + (e >> 1) * 8;
                bf16 hi, lo;
                bsplit(gelu_f(C[mt][nt][e]), &hi, &lo);
                YsH[hh * YL + ll] = hi;
                YsL[hh * YL + ll] = lo;
            }
        }
    __syncthreads();
    // coalesced plane writes: 64 h x 256 l = 2048 uint4 per plane
    #pragma unroll
    for (int i = t; i < 2048; i += 256) {
        int h = i >> 5, q = i & 31;
        size_t base = ((size_t)b * HH + h) * LL + l0 + q * 8;
        *(uint4*)(g_uh + base) = *(const uint4*)&YsH[h * YL + q * 8];
        *(uint4*)(g_ul + base) = *(const uint4*)&YsL[h * YL + q * 8];
    }
}

// ---------------- K3: fused scan; pass-2 direct fragment STG (barrier-free) ----------------
__global__ __launch_bounds__(512) void k_scan_mma()
{
    extern __shared__ char smem[];
    bf16* MHs = (bf16*)(smem + SM_MH);
    bf16* MLs = (bf16*)(smem + SM_ML);
    bf16* VHs = (bf16*)(smem + SM_VH);
    bf16* VLs = (bf16*)(smem + SM_VL);
    bf16* EHs = (bf16*)(smem + SM_EH);
    bf16* ELs = (bf16*)(smem + SM_EL);
    float* SLOC = (float*)(smem + SM_SLOC);
    bf16* SINH = (bf16*)(smem + SM_SINH);
    bf16* SINL = (bf16*)(smem + SM_SINL);
    float2* GBUF = (float2*)(smem + SM_GBUF);
    bf16* B0H = (bf16*)(smem + SM_UB0);
    bf16* B0L = (bf16*)(smem + SM_UB0 + UBUF_HALF);
    bf16* B1H = (bf16*)(smem + SM_UB1);
    bf16* B1L = (bf16*)(smem + SM_UB1 + UBUF_HALF);
    bf16* B2H = (bf16*)(smem + SM_UB2);
    bf16* B2L = (bf16*)(smem + SM_UB2 + UBUF_HALF);

    int t = threadIdx.x;
    int bh = blockIdx.x;
    int h = bh & 63;
    int wid = t >> 5, lane = t & 31;
    int cloc = wid * 8;

    const bf16* guh = g_uh + (size_t)bh * LL;
    const bf16* gul = g_ul + (size_t)bh * LL;

    stage_async(guh, gul, 0, t, B0H, B0L); CP_COMMIT();
    stage_async(guh, gul, 1, t, B1H, B1L); CP_COMMIT();
    stage_async(guh, gul, 2, t, B2H, B2L); CP_COMMIT();

    {
        const u32* gmh = (const u32*)(g_Mh + (size_t)h * 4096);
        const u32* gml = (const u32*)(g_Ml + (size_t)h * 4096);
        u32* smh = (u32*)MHs; u32* sml = (u32*)MLs;
        for (int i = t; i < 2048; i += 512) {
            int r = i >> 5, c = i & 31;
            smh[r * 36 + c] = gmh[i]; sml[r * 36 + c] = gml[i];
        }
        const u32* gvh = (const u32*)(g_Vh + (size_t)h * 2048);
        const u32* gvl = (const u32*)(g_Vl + (size_t)h * 2048);
        u32* svh = (u32*)VHs; u32* svl = (u32*)VLs;
        for (int i = t; i < 1024; i += 512) {
            int r = i >> 5, c = i & 31;
            svh[r * 36 + c] = gvh[i]; svl[r * 36 + c] = gvl[i];
        }
        const u32* geh = (const u32*)(g_Eh + (size_t)h * 2048);
        const u32* gel = (const u32*)(g_El + (size_t)h * 2048);
        u32* seh = (u32*)EHs; u32* sel = (u32*)ELs;
        for (int i = t; i < 1024; i += 512) {
            int r = i >> 4, c = i & 15;
            seh[r * 20 + c] = geh[i]; sel[r * 20 + c] = gel[i];
        }
    }

    float Yreg[64];
    #pragma unroll
    for (int i = 0; i < 64; i++) Yreg[i] = 0.0f;

#define PAIR(P, UHA, ULA, UHB, ULB)                                            \
    {                                                                          \
        float C1a[2][4] = {}, C1b[2][4] = {};                                  \
        _Pragma("unroll")                                                      \
        for (int kt = 0; kt < 4; kt++) {                                       \
            int k0 = kt * 16;                                                  \
            u32 bah[2], bal[2], bbh[2], bbl[2];                                \
            ldsm_x2(bah, UHA, USTR, cloc, k0, lane);                           \
            ldsm_x2(bal, ULA, USTR, cloc, k0, lane);                           \
            ldsm_x2(bbh, UHB, USTR, cloc, k0, lane);                           \
            ldsm_x2(bbl, ULB, USTR, cloc, k0, lane);                           \
            _Pragma("unroll")                                                  \
            for (int mt = 0; mt < 2; mt++) {                                   \
                u32 ah[4], al[4];                                              \
                ldsm_x4(ah, VHs, VSTR, mt * 16, k0, lane);                     \
                ldsm_x4(al, VLs, VSTR, mt * 16, k0, lane);                     \
                mma16816(C1a[mt], ah, bah); mma16816(C1a[mt], ah, bal);        \
                mma16816(C1a[mt], al, bah);                                    \
                mma16816(C1b[mt], ah, bbh); mma16816(C1b[mt], ah, bbl);        \
                mma16816(C1b[mt], al, bbh);                                    \
            }                                                                  \
            _Pragma("unroll")                                                  \
            for (int mt = 0; mt < 4; mt++) {                                   \
                if (kt > mt) continue;                                         \
                u32 ah[4], al[4];                                              \
                ldsm_x4(ah, MHs, MSTR, mt * 16, k0, lane);                     \
                ldsm_x4(al, MLs, MSTR, mt * 16, k0, lane);                     \
                float* Ca = &Yreg[(2 * (P)) * 16 + mt * 4];                    \
                float* Cb = &Yreg[(2 * (P) + 1) * 16 + mt * 4];                \
                mma16816(Ca, ah, bah); mma16816(Ca, ah, bal);                  \
                mma16816(Ca, al, bah);                                         \
                mma16816(Cb, ah, bbh); mma16816(Cb, ah, bbl);                  \
                mma16816(Cb, al, bbh);                                         \
            }                                                                  \
        }                                                                      \
        _Pragma("unroll")                                                      \
        for (int mt = 0; mt < 2; mt++) {                                       \
            int r = mt * 16 + (lane >> 2);                                     \
            int ca = (2 * (P)) * 128 + cloc + (lane & 3) * 2;                  \
            int cb = (2 * (P) + 1) * 128 + cloc + (lane & 3) * 2;              \
            SLOC[r * LSTR + ca] = C1a[mt][0];                                  \
            SLOC[r * LSTR + ca + 1] = C1a[mt][1];                              \
            SLOC[(r + 8) * LSTR + ca] = C1a[mt][2];                            \
            SLOC[(r + 8) * LSTR + ca + 1] = C1a[mt][3];                        \
            SLOC[r * LSTR + cb] = C1b[mt][0];                                  \
            SLOC[r * LSTR + cb + 1] = C1b[mt][1];                              \
            SLOC[(r + 8) * LSTR + cb] = C1b[mt][2];                            \
            SLOC[(r + 8) * LSTR + cb + 1] = C1b[mt][3];                        \
        }                                                                      \
    }

    CP_WAIT(1);
    __syncthreads();
    PAIR(0, B0H, B0L, B1H, B1L)
    __syncthreads();
    stage_async(guh, gul, 3, t, B0H, B0L); CP_COMMIT();
    CP_WAIT(0);
    __syncthreads();
    PAIR(1, B2H, B2L, B0H, B0L)
    __syncthreads();
#undef PAIR

    {
        int n = t & 15, g = t >> 4;
        float2 w64 = g_w64c[h * 16 + n];
        float sr = 0.f, si = 0.f;
        for (int m = 0; m < 16; m++) {
            int c = g * 16 + m;
            float xr = SLOC[n * LSTR + c], xi = SLOC[(16 + n) * LSTR + c];
            float nr = fmaf(w64.x, sr, fmaf(-w64.y, si, xr));
            si = fmaf(w64.x, si, fmaf(w64.y, sr, xi));
            sr = nr;
        }
        GBUF[g * 16 + n] = make_float2(sr, si);
        __syncthreads();
        if (t < 16) {
            float2 wG = g_wGc[h * 16 + t];
            float pr = 0.f, pi = 0.f;
            for (int gg = 0; gg < 32; gg++) {
                float2 tm = GBUF[gg * 16 + t];
                GBUF[gg * 16 + t] = make_float2(pr, pi);
                float nr = fmaf(wG.x, pr, fmaf(-wG.y, pi, tm.x));
                pi = fmaf(wG.x, pi, fmaf(wG.y, pr, tm.y));
                pr = nr;
            }
        }
        __syncthreads();
        float2 I = GBUF[g * 16 + n];
        sr = I.x; si = I.y;
        for (int m = 0; m < 16; m++) {
            int c = g * 16 + m;
            bsplit(sr, &SINH[c * SSTR + n], &SINL[c * SSTR + n]);
            bsplit(si, &SINH[c * SSTR + 16 + n], &SINL[c * SSTR + 16 + n]);
            float xr = SLOC[n * LSTR + c], xi = SLOC[(16 + n) * LSTR + c];
            float nr = fmaf(w64.x, sr, fmaf(-w64.y, si, xr));
            si = fmaf(w64.x, si, fmaf(w64.y, sr, xi));
            sr = nr;
        }
    }
    __syncthreads();

    // ---- pass 2: Y += E@S_in; FiLM; DIRECT fragment STG (no barriers) ----
    float gam = g_gamma[bh];
    float bet = g_beta[bh];
    float* gz = g_z + (size_t)bh * LL;

    #pragma unroll
    for (int q = 0; q < 4; q++) {
        int cglob = q * 128 + cloc;
        #pragma unroll
        for (int kt = 0; kt < 2; kt++) {
            int k0 = kt * 16;
            u32 bh_[2], bl_[2];
            ldsm_x2(bh_, SINH, SSTR, cglob, k0, lane);
            ldsm_x2(bl_, SINL, SSTR, cglob, k0, lane);
            #pragma unroll
            for (int mt = 0; mt < 4; mt++) {
                u32 ah[4], al[4];
                ldsm_x4(ah, EHs, ESTR, mt * 16, k0, lane);
                ldsm_x4(al, ELs, ESTR, mt * 16, k0, lane);
                float* Cm = &Yreg[q * 16 + mt * 4];
                mma16816(Cm, ah, bh_);
                mma16816(Cm, ah, bl_);
                mma16816(Cm, al, bh_);
            }
        }
        #pragma unroll
        for (int mt = 0; mt < 4; mt++) {
            int j = mt * 16 + (lane >> 2);
            int cc = q * 128 + cloc + (lane & 3) * 2;   // global chunk within (b,h)
            const float* Cm = &Yreg[q * 16 + mt * 4];
            gz[cc * 64 + j]           = fmaf(Cm[0], gam, bet);
            gz[(cc + 1) * 64 + j]     = fmaf(Cm[1], gam, bet);
            gz[cc * 64 + j + 8]       = fmaf(Cm[2], gam, bet);
            gz[(cc + 1) * 64 + j + 8] = fmaf(Cm[3], gam, bet);
        }
    }
}

// ---------------- K4: out = x * gelu(z) ----------------
__global__ __launch_bounds__(256) void k_epilogue(const float* __restrict__ x,
                                                  float* __restrict__ out)
{
    __shared__ float zt[64 * 65];
    int t = threadIdx.x;
    int b = blockIdx.x >> 9;
    int tile = blockIdx.x & 511;
    int l0 = tile * 64;
    #pragma unroll
    for (int i = t; i < 1024; i += 256) {
        int hh = i >> 4, q = i & 15;
        float4 v = *reinterpret_cast<const float4*>(
            g_z + ((size_t)b * HH + hh) * LL + l0 + 4 * q);
        float* d = zt + hh * 65 + 4 * q;
        d[0] = v.x; d[1] = v.y; d[2] = v.z; d[3] = v.w;
    }
    __syncthreads();
    #pragma unroll
    for (int i = t; i < 1024; i += 256) {
        int l = i >> 4, hq = i & 15;
        float z0 = zt[(4 * hq + 0) * 65 + l];
        float z1 = zt[(4 * hq + 1) * 65 + l];
        float z2 = zt[(4 * hq + 2) * 65 + l];
        float z3 = zt[(4 * hq + 3) * 65 + l];
        size_t base = ((size_t)b * LL + l0 + l) * HH + 4 * hq;
        float4 xv = *reinterpret_cast<const float4*>(x + base);
        float4 o;
        o.x = xv.x * gelu_f(z0);
        o.y = xv.y * gelu_f(z1);
        o.z = xv.z * gelu_f(z2);
        o.w = xv.w * gelu_f(z3);
        *reinterpret_cast<float4*>(out + base) = o;
    }
}

// ---------------- launch ----------------
extern "C" void kernel_launch(void* const* d_in, const int* in_sizes, int n_in,
                              void* d_out, int out_size)
{
    const float* x      = (const float*)d_in[0];
    const float* cp     = (const float*)d_in[1];
    const float* W0     = (const float*)d_in[2];
    const float* b0     = (const float*)d_in[3];
    const float* W1     = (const float*)d_in[4];
    const float* b1     = (const float*)d_in[5];
    const float* W2     = (const float*)d_in[6];
    const float* b2     = (const float*)d_in[7];
    const float* W_lin  = (const float*)d_in[8];
    const float* b_lin  = (const float*)d_in[9];
    const float* log_dt = (const float*)d_in[10];
    const float* A_re   = (const float*)d_in[11];
    const float* A_im   = (const float*)d_in[12];
    const float* C_re   = (const float*)d_in[13];
    const float* C_im   = (const float*)d_in[14];
    const float* Dv     = (const float*)d_in[15];
    const float* W_film = (const float*)d_in[16];
    const float* b_film = (const float*)d_in[17];
    float* out = (float*)d_out;

    cudaFuncSetAttribute(k_linear_mma, cudaFuncAttributeMaxDynamicSharedMemorySize, LM_TOT);
    cudaFuncSetAttribute(k_scan_mma, cudaFuncAttributeMaxDynamicSharedMemorySize, SM_TOT);

    k_setup_tab<<<HH, 64>>>(log_dt, A_re, A_im, C_re, C_im, Dv);
    k_setup_mlp<<<1, 256>>>(cp, W0, b0, W1, b1, W2, b2, W_film, b_film, W_lin);
    k_linear_mma<<<BB * (LL / 256), 256, LM_TOT>>>(x, b_lin);
    k_scan_mma<<<BB * HH, 512, SM_TOT>>>();
    k_epilogue<<<BB * (LL / 64), 256>>>(x, out);
}

// round 17
// speedup vs baseline: 1.4039x; 1.0064x over previous
#include <cuda_runtime.h>
#include <cuda_bf16.h>
#include <cstdint>
#include <cstddef>

#define BB 16
#define LL 32768
#define HH 64
#define NN 16
#define DMM 32

typedef unsigned long long u64;
typedef uint32_t u32;
typedef __nv_bfloat16 bf16;

// strides (elements)
#define USTR 72
#define MSTR 72
#define VSTR 72
#define ESTR 40
#define SSTR 40
#define LSTR 521

// scan smem (total 227456 <= 232448)
#define SM_MH 0
#define SM_ML 9216
#define SM_VH 18432
#define SM_VL 23040
#define SM_EH 27648
#define SM_EL 32768
#define SM_UB0 37888
#define SM_SLOC 74752
#define SM_UB1 141440
#define SM_UB2 178304
#define SM_SINH 141440
#define SM_SINL 182400
#define SM_GBUF 223360
#define SM_TOT 227456
#define UBUF_HALF 18432

// linear-mma smem (256-l tile, 256 threads)
#define LM_WTH 0
#define LM_WTL 9216
#define LM_BS 18432
#define LM_XH 18688
#define LM_XL 55552
#define LM_YS 18688
#define LM_TOT 92416
#define XSTR 72
#define WSTR 72
#define YL 264

// ---------------- scratch ----------------
__device__ bf16 g_uh[(size_t)BB * HH * LL];
__device__ bf16 g_ul[(size_t)BB * HH * LL];
__device__ float g_z[(size_t)BB * HH * LL];
__device__ bf16 g_Mh[HH * 4096], g_Ml[HH * 4096];
__device__ bf16 g_Vh[HH * 2048], g_Vl[HH * 2048];
__device__ bf16 g_Eh[HH * 2048], g_El[HH * 2048];
__device__ bf16 g_WH[4096], g_WL[4096];
__device__ float2 g_w64c[HH * 16], g_wGc[HH * 16];
__device__ float g_gamma[BB * HH], g_beta[BB * HH];

// ---------------- helpers ----------------
__device__ __forceinline__ float gelu_f(float x) {
    float x3 = x * x * x;
    float z = 0.7978845608028654f * fmaf(0.044715f, x3, x);
    float az = fabsf(z);
    float e = __expf(2.0f * az);
    float t = 1.0f - __fdividef(2.0f, e + 1.0f);
    t = copysignf(t, z);
    return 0.5f * x * (1.0f + t);
}
__device__ __forceinline__ void bsplit(float v, bf16* ph, bf16* pl) {
    bf16 hi = __float2bfloat16(v);
    *ph = hi; *pl = __float2bfloat16(v - __bfloat162float(hi));
}
__device__ __forceinline__ u32 pk2bf(bf16 a, bf16 b) {
    __nv_bfloat162 v; v.x = a; v.y = b; return *reinterpret_cast<u32*>(&v);
}
__device__ __forceinline__ float2 cmulf(float2 a, float2 b) {
    return make_float2(a.x * b.x - a.y * b.y, a.x * b.y + a.y * b.x);
}
__device__ __forceinline__ float2 cpowf(float2 w, int e) {
    float2 r = make_float2(1.0f, 0.0f);
    while (e) {
        if (e & 1) r = cmulf(r, w);
        w = cmulf(w, w);
        e >>= 1;
    }
    return r;
}
__device__ __forceinline__ void mma16816(float* c, const u32* a, const u32* b) {
    asm volatile(
        "mma.sync.aligned.m16n8k16.row.col.f32.bf16.bf16.f32 "
        "{%0,%1,%2,%3}, {%4,%5,%6,%7}, {%8,%9}, {%0,%1,%2,%3};"
        : "+f"(c[0]), "+f"(c[1]), "+f"(c[2]), "+f"(c[3])
        : "r"(a[0]), "r"(a[1]), "r"(a[2]), "r"(a[3]), "r"(b[0]), "r"(b[1]));
}
__device__ __forceinline__ void ldsm_x4(u32* r, const bf16* base, int stride,
                                        int r0, int k0, int lane) {
    const bf16* p = base + (r0 + (lane & 15)) * stride + k0 + (lane >> 4) * 8;
    u32 addr = (u32)__cvta_generic_to_shared(p);
    asm volatile("ldmatrix.sync.aligned.m8n8.x4.shared.b16 {%0,%1,%2,%3}, [%4];"
        : "=r"(r[0]), "=r"(r[1]), "=r"(r[2]), "=r"(r[3]) : "r"(addr));
}
__device__ __forceinline__ void ldsm_x2(u32* r, const bf16* base, int stride,
                                        int n0, int k0, int lane) {
    const bf16* p = base + (n0 + (lane & 7)) * stride + k0 + ((lane >> 3) & 1) * 8;
    u32 addr = (u32)__cvta_generic_to_shared(p);
    asm volatile("ldmatrix.sync.aligned.m8n8.x2.shared.b16 {%0,%1}, [%2];"
        : "=r"(r[0]), "=r"(r[1]) : "r"(addr));
}
__device__ __forceinline__ void cpasync16(void* sdst, const void* gsrc) {
    u32 s = (u32)__cvta_generic_to_shared(sdst);
    asm volatile("cp.async.cg.shared.global [%0], [%1], 16;" :: "r"(s), "l"(gsrc) : "memory");
}
#define CP_COMMIT() asm volatile("cp.async.commit_group;" ::: "memory")
#define CP_WAIT(n) asm volatile("cp.async.wait_group %0;" :: "n"(n) : "memory")

__device__ __forceinline__ void stage_async(const bf16* guh, const bf16* gul,
                                            int q, int t, bf16* UH, bf16* UL) {
    #pragma unroll
    for (int k = 0; k < 2; k++) {
        int f = t + k * 512;
        int c = f >> 3, i0 = (f & 7) * 8;
        cpasync16(&UH[c * USTR + i0], guh + q * 8192 + c * 64 + i0);
        cpasync16(&UL[c * USTR + i0], gul + q * 8192 + c * 64 + i0);
    }
}

// ---------------- K0: per-h tables ----------------
__global__ void k_setup_tab(const float* __restrict__ log_dt,
                            const float* __restrict__ A_re, const float* __restrict__ A_im,
                            const float* __restrict__ C_re, const float* __restrict__ C_im,
                            const float* __restrict__ Dv)
{
    int h = blockIdx.x;
    int j = threadIdx.x;
    __shared__ float2 wf[NN];
    __shared__ float2 c2f[NN];
    __shared__ float Ks[64];

    double dt = exp((double)log_dt[h]);
    if (j < NN) {
        int i = h * NN + j;
        float ar = A_re[i], ai = A_im[i];
        double mre = dt * (double)ar, mim = dt * (double)ai;
        double e1 = exp(mre);
        float wr = (float)(e1 * cos(mim)), wi = (float)(e1 * sin(mim));
        wf[j] = make_float2(wr, wi);
        float den = ar * ar + ai * ai;
        float nr = wr - 1.0f, ni = wi;
        float qr = (nr * ar + ni * ai) / den, qi = (ni * ar - nr * ai) / den;
        float cr = C_re[i], ci = C_im[i];
        c2f[j] = make_float2(2.0f * (cr * qr - ci * qi), 2.0f * (cr * qi + ci * qr));
        float2 w64 = cpowf(make_float2(wr, wi), 64);
        g_w64c[h * 16 + j] = w64;
        g_wGc[h * 16 + j] = cpowf(w64, 16);
    }
    __syncthreads();

    float kacc = 0.0f;
    for (int n = 0; n < NN; n++) {
        float2 w = wf[n];
        float2 c2 = c2f[n];
        float2 wj = cpowf(w, j);
        kacc += c2.x * wj.x - c2.y * wj.y;
        float2 wj1 = cmulf(wj, w);
        bsplit(c2.x * wj1.x - c2.y * wj1.y,
               &g_Eh[h * 2048 + j * 32 + n], &g_El[h * 2048 + j * 32 + n]);
        bsplit(-(c2.x * wj1.y + c2.y * wj1.x),
               &g_Eh[h * 2048 + j * 32 + 16 + n], &g_El[h * 2048 + j * 32 + 16 + n]);
        float2 wv = cpowf(w, 63 - j);
        bsplit(wv.x, &g_Vh[h * 2048 + n * 64 + j], &g_Vl[h * 2048 + n * 64 + j]);
        bsplit(wv.y, &g_Vh[h * 2048 + (16 + n) * 64 + j], &g_Vl[h * 2048 + (16 + n) * 64 + j]);
    }
    Ks[j] = kacc;
    __syncthreads();

    float dD = Dv[h];
    for (int i2 = 0; i2 < 64; i2++) {
        float m = (i2 < j) ? Ks[j - i2] : (i2 == j ? Ks[0] + dD : 0.0f);
        bsplit(m, &g_Mh[h * 4096 + j * 64 + i2], &g_Ml[h * 4096 + j * 64 + i2]);
    }
}

// ---------------- K1: conditioning MLP + FiLM + W pre-split ----------------
__global__ void k_setup_mlp(const float* __restrict__ cp,
                            const float* __restrict__ W0, const float* __restrict__ b0,
                            const float* __restrict__ W1, const float* __restrict__ b1,
                            const float* __restrict__ W2, const float* __restrict__ b2,
                            const float* __restrict__ W_film, const float* __restrict__ b_film,
                            const float* __restrict__ W_lin)
{
    __shared__ float c0[BB * DMM];
    __shared__ float c1[BB * DMM];
    int t = threadIdx.x;
    for (int i = t; i < 4096; i += 256) {
        int k = i >> 6, h = i & 63;
        bsplit(W_lin[i], &g_WH[h * 64 + k], &g_WL[h * 64 + k]);
    }
    for (int i = t; i < BB * DMM; i += blockDim.x) {
        int b = i / DMM, d = i % DMM;
        float v = fmaf(cp[b * 2 + 0], W0[d], fmaf(cp[b * 2 + 1], W0[DMM + d], b0[d]));
        c0[i] = gelu_f(v);
    }
    __syncthreads();
    for (int i = t; i < BB * DMM; i += blockDim.x) {
        int b = i / DMM, d = i % DMM;
        float v = b1[d];
        for (int k = 0; k < DMM; k++) v = fmaf(c0[b * DMM + k], W1[k * DMM + d], v);
        c1[i] = gelu_f(v);
    }
    __syncthreads();
    for (int i = t; i < BB * DMM; i += blockDim.x) {
        int b = i / DMM, d = i % DMM;
        float v = b2[d];
        for (int k = 0; k < DMM; k++) v = fmaf(c1[b * DMM + k], W2[k * DMM + d], v);
        c0[i] = gelu_f(v);
    }
    __syncthreads();
    for (int i = t; i < BB * 2 * HH; i += blockDim.x) {
        int b = i / (2 * HH), j = i % (2 * HH);
        float v = b_film[j];
        for (int k = 0; k < DMM; k++) v = fmaf(c0[b * DMM + k], W_film[k * 2 * HH + j], v);
        if (j < HH) g_gamma[b * HH + j] = v;
        else        g_beta[b * HH + j - HH] = v;
    }
}

// ---------------- K2: 256-l tile, 256 threads, cp.async W, fused x staging ----------------
__global__ __launch_bounds__(256, 2) void k_linear_mma(const float* __restrict__ x,
                                                       const float* __restrict__ bias)
{
    extern __shared__ char sm[];
    bf16* WtH = (bf16*)(sm + LM_WTH);
    bf16* WtL = (bf16*)(sm + LM_WTL);
    float* bs = (float*)(sm + LM_BS);
    bf16* XH = (bf16*)(sm + LM_XH);
    bf16* XL = (bf16*)(sm + LM_XL);
    bf16* YsH = (bf16*)(sm + LM_YS);   // overlays XH/XL after MMA
    bf16* YsL = YsH + 64 * YL;

    int t = threadIdx.x, wid = t >> 5, lane = t & 31;
    int b = blockIdx.x >> 7, tile = blockIdx.x & 127;
    int l0 = tile * 256;

    // W staging via cp.async (pre-split bf16, pure 16B copies with pad)
    #pragma unroll
    for (int k = 0; k < 2; k++) {
        int f = t + k * 256;               // 0..511 : 64 rows x 8 chunks
        int r = f >> 3, c8 = (f & 7) * 8;
        cpasync16(&WtH[r * WSTR + c8], g_WH + r * 64 + c8);
        cpasync16(&WtL[r * WSTR + c8], g_WL + r * 64 + c8);
    }
    CP_COMMIT();
    if (t < 64) bs[t] = bias[t];

    // fused x load-convert-store (low register pressure; ptxas pipelines)
    const float4* xg4 = (const float4*)(x + ((size_t)b * LL + l0) * HH);
    #pragma unroll
    for (int kk = 0; kk < 16; kk++) {
        int f = t + kk * 256;
        float4 v = xg4[f];
        int l = f >> 4, i0 = (f & 15) * 4;
        bf16 h0, l0b, h1, l1b, h2, l2b, h3, l3b;
        bsplit(v.x, &h0, &l0b); bsplit(v.y, &h1, &l1b);
        bsplit(v.z, &h2, &l2b); bsplit(v.w, &h3, &l3b);
        *(u32*)&XH[l * XSTR + i0] = pk2bf(h0, h1);
        *(u32*)&XH[l * XSTR + i0 + 2] = pk2bf(h2, h3);
        *(u32*)&XL[l * XSTR + i0] = pk2bf(l0b, l1b);
        *(u32*)&XL[l * XSTR + i0 + 2] = pk2bf(l2b, l3b);
    }
    CP_WAIT(0);
    __syncthreads();

    // warp tile: 32 l x 64 h (8 warps cover 256 l)
    float C[2][8][4];
    #pragma unroll
    for (int mt = 0; mt < 2; mt++)
        #pragma unroll
        for (int nt = 0; nt < 8; nt++) {
            int c0 = nt * 8 + (lane & 3) * 2;
            C[mt][nt][0] = bs[c0]; C[mt][nt][1] = bs[c0 + 1];
            C[mt][nt][2] = bs[c0]; C[mt][nt][3] = bs[c0 + 1];
        }
    #pragma unroll
    for (int kt = 0; kt < 4; kt++) {
        int k0 = kt * 16;
        u32 ah[2][4], al[2][4];
        #pragma unroll
        for (int mt = 0; mt < 2; mt++) {
            ldsm_x4(ah[mt], XH, XSTR, wid * 32 + mt * 16, k0, lane);
            ldsm_x4(al[mt], XL, XSTR, wid * 32 + mt * 16, k0, lane);
        }
        #pragma unroll
        for (int nt = 0; nt < 8; nt++) {
            u32 bh[2], bl[2];
            ldsm_x2(bh, WtH, WSTR, nt * 8, k0, lane);
            ldsm_x2(bl, WtL, WSTR, nt * 8, k0, lane);
            #pragma unroll
            for (int mt = 0; mt < 2; mt++) {
                mma16816(C[mt][nt], ah[mt], bh);
                mma16816(C[mt][nt], ah[mt], bl);
                mma16816(C[mt][nt], al[mt], bh);
            }
        }
    }
    __syncthreads();   // all X reads done before Ys overlay writes
    #pragma unroll
    for (int mt = 0; mt < 2; mt++)
        #pragma unroll
        for (int nt = 0; nt < 8; nt++) {
            int l = wid * 32 + mt * 16 + (lane >> 2);
            int h0 = nt * 8 + (lane & 3) * 2;
            #pragma unroll
            for (int e = 0; e < 4; e++) {
                int hh = h0 + (e & 1);
                int ll = l + (e >> 1) * 8;
                bf16 hi, lo;
                bsplit(gelu_f(C[mt][nt][e]), &hi, &lo);
                YsH[hh * YL + ll] = hi;
                YsL[hh * YL + ll] = lo;
            }
        }
    __syncthreads();
    // coalesced plane writes: 64 h x 256 l = 2048 uint4 per plane
    #pragma unroll
    for (int i = t; i < 2048; i += 256) {
        int h = i >> 5, q = i & 31;
        size_t base = ((size_t)b * HH + h) * LL + l0 + q * 8;
        *(uint4*)(g_uh + base) = *(const uint4*)&YsH[h * YL + q * 8];
        *(uint4*)(g_ul + base) = *(const uint4*)&YsL[h * YL + q * 8];
    }
}

// ---------------- K3: fused scan; pass-2 direct fragment STG (barrier-free) ----------------
__global__ __launch_bounds__(512) void k_scan_mma()
{
    extern __shared__ char smem[];
    bf16* MHs = (bf16*)(smem + SM_MH);
    bf16* MLs = (bf16*)(smem + SM_ML);
    bf16* VHs = (bf16*)(smem + SM_VH);
    bf16* VLs = (bf16*)(smem + SM_VL);
    bf16* EHs = (bf16*)(smem + SM_EH);
    bf16* ELs = (bf16*)(smem + SM_EL);
    float* SLOC = (float*)(smem + SM_SLOC);
    bf16* SINH = (bf16*)(smem + SM_SINH);
    bf16* SINL = (bf16*)(smem + SM_SINL);
    float2* GBUF = (float2*)(smem + SM_GBUF);
    bf16* B0H = (bf16*)(smem + SM_UB0);
    bf16* B0L = (bf16*)(smem + SM_UB0 + UBUF_HALF);
    bf16* B1H = (bf16*)(smem + SM_UB1);
    bf16* B1L = (bf16*)(smem + SM_UB1 + UBUF_HALF);
    bf16* B2H = (bf16*)(smem + SM_UB2);
    bf16* B2L = (bf16*)(smem + SM_UB2 + UBUF_HALF);

    int t = threadIdx.x;
    int bh = blockIdx.x;
    int h = bh & 63;
    int wid = t >> 5, lane = t & 31;
    int cloc = wid * 8;

    const bf16* guh = g_uh + (size_t)bh * LL;
    const bf16* gul = g_ul + (size_t)bh * LL;

    stage_async(guh, gul, 0, t, B0H, B0L); CP_COMMIT();
    stage_async(guh, gul, 1, t, B1H, B1L); CP_COMMIT();
    stage_async(guh, gul, 2, t, B2H, B2L); CP_COMMIT();

    {
        const u32* gmh = (const u32*)(g_Mh + (size_t)h * 4096);
        const u32* gml = (const u32*)(g_Ml + (size_t)h * 4096);
        u32* smh = (u32*)MHs; u32* sml = (u32*)MLs;
        for (int i = t; i < 2048; i += 512) {
            int r = i >> 5, c = i & 31;
            smh[r * 36 + c] = gmh[i]; sml[r * 36 + c] = gml[i];
        }
        const u32* gvh = (const u32*)(g_Vh + (size_t)h * 2048);
        const u32* gvl = (const u32*)(g_Vl + (size_t)h * 2048);
        u32* svh = (u32*)VHs; u32* svl = (u32*)VLs;
        for (int i = t; i < 1024; i += 512) {
            int r = i >> 5, c = i & 31;
            svh[r * 36 + c] = gvh[i]; svl[r * 36 + c] = gvl[i];
        }
        const u32* geh = (const u32*)(g_Eh + (size_t)h * 2048);
        const u32* gel = (const u32*)(g_El + (size_t)h * 2048);
        u32* seh = (u32*)EHs; u32* sel = (u32*)ELs;
        for (int i = t; i < 1024; i += 512) {
            int r = i >> 4, c = i & 15;
            seh[r * 20 + c] = geh[i]; sel[r * 20 + c] = gel[i];
        }
    }

    float Yreg[64];
    #pragma unroll
    for (int i = 0; i < 64; i++) Yreg[i] = 0.0f;

#define PAIR(P, UHA, ULA, UHB, ULB)                                            \
    {                                                                          \
        float C1a[2][4] = {}, C1b[2][4] = {};                                  \
        _Pragma("unroll")                                                      \
        for (int kt = 0; kt < 4; kt++) {                                       \
            int k0 = kt * 16;                                                  \
            u32 bah[2], bal[2], bbh[2], bbl[2];                                \
            ldsm_x2(bah, UHA, USTR, cloc, k0, lane);                           \
            ldsm_x2(bal, ULA, USTR, cloc, k0, lane);                           \
            ldsm_x2(bbh, UHB, USTR, cloc, k0, lane);                           \
            ldsm_x2(bbl, ULB, USTR, cloc, k0, lane);                           \
            _Pragma("unroll")                                                  \
            for (int mt = 0; mt < 2; mt++) {                                   \
                u32 ah[4], al[4];                                              \
                ldsm_x4(ah, VHs, VSTR, mt * 16, k0, lane);                     \
                ldsm_x4(al, VLs, VSTR, mt * 16, k0, lane);                     \
                mma16816(C1a[mt], ah, bah); mma16816(C1a[mt], ah, bal);        \
                mma16816(C1a[mt], al, bah);                                    \
                mma16816(C1b[mt], ah, bbh); mma16816(C1b[mt], ah, bbl);        \
                mma16816(C1b[mt], al, bbh);                                    \
            }                                                                  \
            _Pragma("unroll")                                                  \
            for (int mt = 0; mt < 4; mt++) {                                   \
                if (kt > mt) continue;                                         \
                u32 ah[4], al[4];                                              \
                ldsm_x4(ah, MHs, MSTR, mt * 16, k0, lane);                     \
                ldsm_x4(al, MLs, MSTR, mt * 16, k0, lane);                     \
                float* Ca = &Yreg[(2 * (P)) * 16 + mt * 4];                    \
                float* Cb = &Yreg[(2 * (P) + 1) * 16 + mt * 4];                \
                mma16816(Ca, ah, bah); mma16816(Ca, ah, bal);                  \
                mma16816(Ca, al, bah);                                         \
                mma16816(Cb, ah, bbh); mma16816(Cb, ah, bbl);                  \
                mma16816(Cb, al, bbh);                                         \
            }                                                                  \
        }                                                                      \
        _Pragma("unroll")                                                      \
        for (int mt = 0; mt < 2; mt++) {                                       \
            int r = mt * 16 + (lane >> 2);                                     \
            int ca = (2 * (P)) * 128 + cloc + (lane & 3) * 2;                  \
            int cb = (2 * (P) + 1) * 128 + cloc + (lane & 3) * 2;              \
            SLOC[r * LSTR + ca] = C1a[mt][0];                                  \
            SLOC[r * LSTR + ca + 1] = C1a[mt][1];                              \
            SLOC[(r + 8) * LSTR + ca] = C1a[mt][2];                            \
            SLOC[(r + 8) * LSTR + ca + 1] = C1a[mt][3];                        \
            SLOC[r * LSTR + cb] = C1b[mt][0];                                  \
            SLOC[r * LSTR + cb + 1] = C1b[mt][1];                              \
            SLOC[(r + 8) * LSTR + cb] = C1b[mt][2];                            \
            SLOC[(r + 8) * LSTR + cb + 1] = C1b[mt][3];                        \
        }                                                                      \
    }

    CP_WAIT(1);
    __syncthreads();
    PAIR(0, B0H, B0L, B1H, B1L)
    __syncthreads();
    stage_async(guh, gul, 3, t, B0H, B0L); CP_COMMIT();
    CP_WAIT(0);
    __syncthreads();
    PAIR(1, B2H, B2L, B0H, B0L)
    __syncthreads();
#undef PAIR

    {
        int n = t & 15, g = t >> 4;
        float2 w64 = g_w64c[h * 16 + n];
        float sr = 0.f, si = 0.f;
        for (int m = 0; m < 16; m++) {
            int c = g * 16 + m;
            float xr = SLOC[n * LSTR + c], xi = SLOC[(16 + n) * LSTR + c];
            float nr = fmaf(w64.x, sr, fmaf(-w64.y, si, xr));
            si = fmaf(w64.x, si, fmaf(w64.y, sr, xi));
            sr = nr;
        }
        GBUF[g * 16 + n] = make_float2(sr, si);
        __syncthreads();
        if (t < 16) {
            float2 wG = g_wGc[h * 16 + t];
            float pr = 0.f, pi = 0.f;
            for (int gg = 0; gg < 32; gg++) {
                float2 tm = GBUF[gg * 16 + t];
                GBUF[gg * 16 + t] = make_float2(pr, pi);
                float nr = fmaf(wG.x, pr, fmaf(-wG.y, pi, tm.x));
                pi = fmaf(wG.x, pi, fmaf(wG.y, pr, tm.y));
                pr = nr;
            }
        }
        __syncthreads();
        float2 I = GBUF[g * 16 + n];
        sr = I.x; si = I.y;
        for (int m = 0; m < 16; m++) {
            int c = g * 16 + m;
            bsplit(sr, &SINH[c * SSTR + n], &SINL[c * SSTR + n]);
            bsplit(si, &SINH[c * SSTR + 16 + n], &SINL[c * SSTR + 16 + n]);
            float xr = SLOC[n * LSTR + c], xi = SLOC[(16 + n) * LSTR + c];
            float nr = fmaf(w64.x, sr, fmaf(-w64.y, si, xr));
            si = fmaf(w64.x, si, fmaf(w64.y, sr, xi));
            sr = nr;
        }
    }
    __syncthreads();

    // ---- pass 2: Y += E@S_in; FiLM; DIRECT fragment STG (no barriers) ----
    float gam = g_gamma[bh];
    float bet = g_beta[bh];
    float* gz = g_z + (size_t)bh * LL;

    #pragma unroll
    for (int q = 0; q < 4; q++) {
        int cglob = q * 128 + cloc;
        #pragma unroll
        for (int kt = 0; kt < 2; kt++) {
            int k0 = kt * 16;
            u32 bh_[2], bl_[2];
            ldsm_x2(bh_, SINH, SSTR, cglob, k0, lane);
            ldsm_x2(bl_, SINL, SSTR, cglob, k0, lane);
            #pragma unroll
            for (int mt = 0; mt < 4; mt++) {
                u32 ah[4], al[4];
                ldsm_x4(ah, EHs, ESTR, mt * 16, k0, lane);
                ldsm_x4(al, ELs, ESTR, mt * 16, k0, lane);
                float* Cm = &Yreg[q * 16 + mt * 4];
                mma16816(Cm, ah, bh_);
                mma16816(Cm, ah, bl_);
                mma16816(Cm, al, bh_);
            }
        }
        #pragma unroll
        for (int mt = 0; mt < 4; mt++) {
            int j = mt * 16 + (lane >> 2);
            int cc = q * 128 + cloc + (lane & 3) * 2;   // global chunk within (b,h)
            const float* Cm = &Yreg[q * 16 + mt * 4];
            gz[cc * 64 + j]           = fmaf(Cm[0], gam, bet);
            gz[(cc + 1) * 64 + j]     = fmaf(Cm[1], gam, bet);
            gz[cc * 64 + j + 8]       = fmaf(Cm[2], gam, bet);
            gz[(cc + 1) * 64 + j + 8] = fmaf(Cm[3], gam, bet);
        }
    }
}

// ---------------- K4: out = x * gelu(z) ----------------
__global__ __launch_bounds__(256) void k_epilogue(const float* __restrict__ x,
                                                  float* __restrict__ out)
{
    __shared__ float zt[64 * 65];
    int t = threadIdx.x;
    int b = blockIdx.x >> 9;
    int tile = blockIdx.x & 511;
    int l0 = tile * 64;
    #pragma unroll
    for (int i = t; i < 1024; i += 256) {
        int hh = i >> 4, q = i & 15;
        float4 v = *reinterpret_cast<const float4*>(
            g_z + ((size_t)b * HH + hh) * LL + l0 + 4 * q);
        float* d = zt + hh * 65 + 4 * q;
        d[0] = v.x; d[1] = v.y; d[2] = v.z; d[3] = v.w;
    }
    __syncthreads();
    #pragma unroll
    for (int i = t; i < 1024; i += 256) {
        int l = i >> 4, hq = i & 15;
        float z0 = zt[(4 * hq + 0) * 65 + l];
        float z1 = zt[(4 * hq + 1) * 65 + l];
        float z2 = zt[(4 * hq + 2) * 65 + l];
        float z3 = zt[(4 * hq + 3) * 65 + l];
        size_t base = ((size_t)b * LL + l0 + l) * HH + 4 * hq;
        float4 xv = *reinterpret_cast<const float4*>(x + base);
        float4 o;
        o.x = xv.x * gelu_f(z0);
        o.y = xv.y * gelu_f(z1);
        o.z = xv.z * gelu_f(z2);
        o.w = xv.w * gelu_f(z3);
        *reinterpret_cast<float4*>(out + base) = o;
    }
}

// ---------------- launch ----------------
extern "C" void kernel_launch(void* const* d_in, const int* in_sizes, int n_in,
                              void* d_out, int out_size)
{
    const float* x      = (const float*)d_in[0];
    const float* cp     = (const float*)d_in[1];
    const float* W0     = (const float*)d_in[2];
    const float* b0     = (const float*)d_in[3];
    const float* W1     = (const float*)d_in[4];
    const float* b1     = (const float*)d_in[5];
    const float* W2     = (const float*)d_in[6];
    const float* b2     = (const float*)d_in[7];
    const float* W_lin  = (const float*)d_in[8];
    const float* b_lin  = (const float*)d_in[9];
    const float* log_dt = (const float*)d_in[10];
    const float* A_re   = (const float*)d_in[11];
    const float* A_im   = (const float*)d_in[12];
    const float* C_re   = (const float*)d_in[13];
    const float* C_im   = (const float*)d_in[14];
    const float* Dv     = (const float*)d_in[15];
    const float* W_film = (const float*)d_in[16];
    const float* b_film = (const float*)d_in[17];
    float* out = (float*)d_out;

    cudaFuncSetAttribute(k_linear_mma, cudaFuncAttributeMaxDynamicSharedMemorySize, LM_TOT);
    cudaFuncSetAttribute(k_scan_mma, cudaFuncAttributeMaxDynamicSharedMemorySize, SM_TOT);

    k_setup_tab<<<HH, 64>>>(log_dt, A_re, A_im, C_re, C_im, Dv);
    k_setup_mlp<<<1, 256>>>(cp, W0, b0, W1, b1, W2, b2, W_film, b_film, W_lin);
    k_linear_mma<<<BB * (LL / 256), 256, LM_TOT>>>(x, b_lin);
    k_scan_mma<<<BB * HH, 512, SM_TOT>>>();
    k_epilogue<<<BB * (LL / 64), 256>>>(x, out);
}